// round 10
// baseline (speedup 1.0000x reference)
#include <cuda_runtime.h>
#include <cuda_bf16.h>
#include <cstdint>

// ----------------------------------------------------------------------------
// RadianceRenderer R10: persistent blocks. Fragment bank + weights staged into
// SMEM ONCE per block (cp.async), then the block loops over ~28 rays running
// the verified register-chained HMMA MLP (R8/R9 math). Weight L2 traffic /27.7.
// Grid = 296 = 148 SMs x 2 blocks. Block = 128 threads, 1 ray per iteration.
// ----------------------------------------------------------------------------

typedef unsigned long long ull;
typedef unsigned int u32;

#define GRID 296
#define N_RAYS 8192

// fragment-ordered B operands in GLOBAL (written by prep kernel):
// uint4 = {hi(k0,k0+1), hi(k0+8,k0+9), lo.., lo..}; [tile][lane].
// W2 @0 (128 tiles), feat @4096 (24), c1 @4864 (32: 0-15 feat rows, 16-31 ynm),
// c2 @5888 (8).
__device__ __align__(16) uint4 g_Bf[6144];

__device__ __forceinline__ void cpa16(u32 dst, const void* src) {
    asm volatile("cp.async.ca.shared.global [%0], [%1], 16;" :: "r"(dst), "l"(src));
}
__device__ __forceinline__ void cpa_commit() {
    asm volatile("cp.async.commit_group;" ::: "memory");
}
template <int N>
__device__ __forceinline__ void cpa_wait() {
    asm volatile("cp.async.wait_group %0;" :: "n"(N) : "memory");
}
__device__ __forceinline__ u32 smem_u32(const void* p) {
    return (u32)__cvta_generic_to_shared(p);
}

__device__ __forceinline__ void mma16816(float c[4], u32 a0, u32 a1, u32 a2, u32 a3,
                                         u32 b0, u32 b1) {
    asm volatile(
        "mma.sync.aligned.m16n8k16.row.col.f32.bf16.bf16.f32 "
        "{%0,%1,%2,%3}, {%4,%5,%6,%7}, {%8,%9}, {%0,%1,%2,%3};"
        : "+f"(c[0]), "+f"(c[1]), "+f"(c[2]), "+f"(c[3])
        : "r"(a0), "r"(a1), "r"(a2), "r"(a3), "r"(b0), "r"(b1));
}

__device__ __forceinline__ void split_pack(float v0, float v1, u32& hi, u32& lo) {
    __nv_bfloat16 h0 = __float2bfloat16(v0), h1 = __float2bfloat16(v1);
    hi = (u32)__bfloat16_as_ushort(h0) | ((u32)__bfloat16_as_ushort(h1) << 16);
    __nv_bfloat16 l0 = __float2bfloat16(v0 - __bfloat162float(h0));
    __nv_bfloat16 l1 = __float2bfloat16(v1 - __bfloat162float(h1));
    lo = (u32)__bfloat16_as_ushort(l0) | ((u32)__bfloat16_as_ushort(l1) << 16);
}

// ---------- prep: pack all B operands fragment-ordered (verified R7/R8) ----------
__global__ void prep_all(const float* __restrict__ W2, const float* __restrict__ Wf,
                         const float* __restrict__ Wd, const float* __restrict__ Wc1,
                         const float* __restrict__ Wc2) {
    int b = blockIdx.x;
    int lane = threadIdx.x;
    int kq = (lane & 3) * 2, nq = lane >> 2;
    float x0, x1, x2, x3;
    uint4* dst;
    if (b < 128) {
        int ks = b >> 4, nt = b & 15;
        int k0 = ks * 16 + kq, n = nt * 8 + nq;
        x0 = W2[k0 * 128 + n];
        x1 = W2[(k0 + 1) * 128 + n];
        x2 = W2[(k0 + 8) * 128 + n];
        x3 = W2[(k0 + 9) * 128 + n];
        dst = g_Bf + b * 32 + lane;
    } else if (b < 152) {
        int idx = b - 128, ks = idx / 3, nt = idx - ks * 3;
        int k0 = ks * 16 + kq, n = nt * 8 + nq;
        auto val = [&](int k) -> float {
            if (n < 16) return Wf[k * 16 + n];
            if (n == 16) return Wd[k];
            return 0.f;
        };
        x0 = val(k0); x1 = val(k0 + 1); x2 = val(k0 + 8); x3 = val(k0 + 9);
        dst = g_Bf + 4096 + idx * 32 + lane;
    } else if (b < 184) {
        int idx = b - 152, ks = idx >> 4, nt = idx & 15;
        int k0 = ks * 16 + kq, n = nt * 8 + nq;
        x0 = Wc1[k0 * 128 + n];
        x1 = Wc1[(k0 + 1) * 128 + n];
        x2 = Wc1[(k0 + 8) * 128 + n];
        x3 = Wc1[(k0 + 9) * 128 + n];
        dst = g_Bf + 4864 + idx * 32 + lane;
    } else {
        int ks = b - 184;
        int k0 = ks * 16 + kq, n = nq;
        auto val = [&](int k) -> float { return (n < 3) ? Wc2[k * 3 + n] : 0.f; };
        x0 = val(k0); x1 = val(k0 + 1); x2 = val(k0 + 8); x3 = val(k0 + 9);
        dst = g_Bf + 5888 + ks * 32 + lane;
    }
    uint4 v;
    split_pack(x0, x1, v.x, v.z);
    split_pack(x2, x3, v.y, v.w);
    *dst = v;
}

// ---------- main kernel ----------
// smem (floats): sB uint4 region [0,22528) = 90112 B
//   wsm  22528..23328  (W1 0..384, b1 384..512, b2 512..640, bc1 640..768,
//                       bf 768..784, bd 784, bc2 785..788)
//   wy   23328..25376  (Wc1 ynm rows [16][128])
//   sxyz 25376(192) sts 25568(64) ssig 25632(64) sins 25696(64) synm 25760(16)
//   sc0 25776(64) sc1 25840(64) sc2 25904(64) sred 25968(16) shcY 25984(128)
// total 26112 floats = 104448 B -> 2 blocks/SM.
__global__ __launch_bounds__(128, 2) void radiance_kernel(
    const float* __restrict__ rays_o, const float* __restrict__ rays_d,
    const float* __restrict__ aabb,
    const float* __restrict__ W1, const float* __restrict__ b1,
    const float* __restrict__ W2, const float* __restrict__ b2,
    const float* __restrict__ Wd, const float* __restrict__ bd,
    const float* __restrict__ Wf, const float* __restrict__ bf,
    const float* __restrict__ Wc1, const float* __restrict__ bc1,
    const float* __restrict__ Wc2, const float* __restrict__ bc2,
    float* __restrict__ out) {
    extern __shared__ float sm[];
    const uint4* sB = (const uint4*)sm;
    float* wsm  = sm + 22528;
    float* wy   = sm + 23328;
    float* sxyz = sm + 25376;
    float* sts  = sm + 25568;
    float* ssig = sm + 25632;
    float* sins = sm + 25696;
    float* synm = sm + 25760;
    float* sc0  = sm + 25776;
    float* sc1  = sm + 25840;
    float* sc2  = sm + 25904;
    float* sred = sm + 25968;
    float* shcY = sm + 25984;

    const int tid = threadIdx.x;
    const int lane = tid & 31;
    const int wid = tid >> 5;
    const int pb = wid * 16;
    const int r0 = lane >> 2;
    const int p0 = pb + r0, p1 = p0 + 8;
    const int kq = (lane & 3) * 2;
    const u32 sBu = smem_u32(sm);

    // ================= one-time staging (per block) =================
    {
#pragma unroll
        for (int i = 0; i < 32; i++)   // W2 fragments (64KB)
            cpa16(sBu + (u32)(tid + i * 128) * 16u, g_Bf + tid + i * 128);
#pragma unroll
        for (int i = 0; i < 6; i++)    // feat fragments
            cpa16(sBu + (u32)(4096 + tid + i * 128) * 16u, g_Bf + 4096 + tid + i * 128);
#pragma unroll
        for (int i = 0; i < 4; i++)    // c1 feat-row fragments
            cpa16(sBu + (u32)(4864 + tid + i * 128) * 16u, g_Bf + 4864 + tid + i * 128);
#pragma unroll
        for (int i = 0; i < 2; i++)    // c2 fragments
            cpa16(sBu + (u32)(5376 + tid + i * 128) * 16u, g_Bf + 5888 + tid + i * 128);
        u32 wu = smem_u32(wsm);
        if (tid < 96) cpa16(wu + tid * 16u, W1 + tid * 4);
        else cpa16(wu + 1536u + (tid - 96) * 16u, b1 + (tid - 96) * 4);
        if (tid < 32) cpa16(wu + 2048u + tid * 16u, b2 + tid * 4);
        else if (tid < 64) cpa16(wu + 2560u + (tid - 32) * 16u, bc1 + (tid - 32) * 4);
        else if (tid < 68) cpa16(wu + 3072u + (tid - 64) * 16u, bf + (tid - 64) * 4);
        u32 wyu = smem_u32(wy);
#pragma unroll
        for (int i = 0; i < 4; i++)    // Wc1 ynm rows (8KB)
            cpa16(wyu + (u32)(tid + i * 128) * 16u, Wc1 + 2048 + (tid + i * 128) * 4);
        cpa_commit();
        if (tid == 68) wsm[784] = __ldg(bd);
        if (tid >= 69 && tid < 72) wsm[785 + tid - 69] = __ldg(bc2 + tid - 69);
    }
    float a0x = aabb[0], a0y = aabb[1], a0z = aabb[2];
    float a1x = aabb[3], a1y = aabb[4], a1z = aabb[5];
    cpa_wait<0>();
    __syncthreads();  // staging + bd/bc2 visible

    // ================= per-ray loop =================
#pragma unroll 1
    for (int ray = blockIdx.x; ray < N_RAYS; ray += GRID) {
        // ---- ray setup ----
        float ox = rays_o[ray * 3 + 0], oy = rays_o[ray * 3 + 1], oz = rays_o[ray * 3 + 2];
        float dx = rays_d[ray * 3 + 0], dy = rays_d[ray * 3 + 1], dz = rays_d[ray * 3 + 2];
        float ix = 1.f / dx, iy = 1.f / dy, iz = 1.f / dz;
        float t1x = (a0x - ox) * ix, t2x = (a1x - ox) * ix;
        float t1y = (a0y - oy) * iy, t2y = (a1y - oy) * iy;
        float t1z = (a0z - oz) * iz, t2z = (a1z - oz) * iz;
        float tn = fmaxf(fmaxf(fminf(t1x, t2x), fminf(t1y, t2y)), fminf(t1z, t2z));
        tn = fmaxf(tn, 0.f);
        float tf = fminf(fminf(fmaxf(t1x, t2x), fmaxf(t1y, t2y)), fmaxf(t1z, t2z));
        tf = fminf(tf, 10.f);
        bool active = tn < tf;
        if (!active) { tn = 0.f; tf = 1.f; }
        float dnorm = sqrtf(dx * dx + dy * dy + dz * dz);

        if (tid == 0) {
            float inv = 1.f / dnorm;
            float x = dx * inv, y = dy * inv, z = dz * inv;
            float x2 = x * x, y2 = y * y, z2 = z * z;
            synm[0]  = 0.282094791773878f;
            synm[1]  = -0.488602511902920f * y;
            synm[2]  = 0.488602511902920f * z;
            synm[3]  = -0.488602511902920f * x;
            synm[4]  = 1.092548430592079f * x * y;
            synm[5]  = -1.092548430592079f * y * z;
            synm[6]  = 0.315391565252520f * (3.0f * z2 - 1.0f);
            synm[7]  = -1.092548430592079f * x * z;
            synm[8]  = 0.546274215296040f * (x2 - y2);
            synm[9]  = -0.590043589926644f * y * (3.0f * x2 - y2);
            synm[10] = 2.890611442640554f * x * y * z;
            synm[11] = -0.457045799464466f * y * (5.0f * z2 - 1.0f);
            synm[12] = 0.373176332590115f * z * (5.0f * z2 - 3.0f);
            synm[13] = -0.457045799464466f * x * (5.0f * z2 - 1.0f);
            synm[14] = 1.445305721320277f * z * (x2 - y2);
            synm[15] = -0.590043589926644f * x * (x2 - 3.0f * y2);
        }
        if (tid < 64) {
            float fr = (tid + 0.5f) * (1.f / 64.f);
            float t = tn + fr * (tf - tn);
            sts[tid] = t;
            float px = fmaf(dx, t, ox), py = fmaf(dy, t, oy), pz = fmaf(dz, t, oz);
            float nx = (px - a0x) / (a1x - a0x) * 2.f - 1.f;
            float ny = (py - a0y) / (a1y - a0y) * 2.f - 1.f;
            float nz = (pz - a0z) / (a1z - a0z) * 2.f - 1.f;
            sxyz[tid * 3 + 0] = nx;
            sxyz[tid * 3 + 1] = ny;
            sxyz[tid * 3 + 2] = nz;
            bool inside = (nx >= -1.f) && (nx <= 1.f) && (ny >= -1.f) && (ny <= 1.f) &&
                          (nz >= -1.f) && (nz <= 1.f);
            sins[tid] = inside ? 1.f : 0.f;
        }
        __syncthreads();  // (1) setup visible

        // ---- hcY: point-invariant ynm @ Wc1 (from smem wy) ----
        {
            float acc = 0.f;
#pragma unroll
            for (int j = 0; j < 16; j++)
                acc = fmaf(synm[j], wy[j * 128 + tid], acc);
            shcY[tid] = acc;
        }

        // ======== layer 2 (W2) via HMMA: c[16][4] = h1 @ W2 ========
        float c[16][4];
#pragma unroll
        for (int nt = 0; nt < 16; nt++)
#pragma unroll
            for (int i = 0; i < 4; i++) c[nt][i] = 0.f;
        {
            float P0x = sxyz[p0 * 3], P0y = sxyz[p0 * 3 + 1], P0z = sxyz[p0 * 3 + 2];
            float P1x = sxyz[p1 * 3], P1y = sxyz[p1 * 3 + 1], P1z = sxyz[p1 * 3 + 2];
#pragma unroll 1
            for (int ks = 0; ks < 8; ks++) {
                int j0 = ks * 16 + kq;
                float v[8];
#pragma unroll
                for (int q = 0; q < 4; q++) {
                    int j = j0 + (q & 1) + (q >> 1) * 8;
                    float w0 = wsm[j], w1 = wsm[128 + j], w2 = wsm[256 + j];
                    float bb = wsm[384 + j];
                    float h0 = fmaf(P0x, w0, bb);
                    h0 = fmaf(P0y, w1, h0);
                    h0 = fmaf(P0z, w2, h0);
                    float h1v = fmaf(P1x, w0, bb);
                    h1v = fmaf(P1y, w1, h1v);
                    h1v = fmaf(P1z, w2, h1v);
                    v[q] = fmaxf(h0, 0.f);
                    v[4 + q] = fmaxf(h1v, 0.f);
                }
                u32 ahi[4], alo[4];
                split_pack(v[0], v[1], ahi[0], alo[0]);
                split_pack(v[4], v[5], ahi[1], alo[1]);
                split_pack(v[2], v[3], ahi[2], alo[2]);
                split_pack(v[6], v[7], ahi[3], alo[3]);
                const uint4* gb = sB + ks * 16 * 32 + lane;
#pragma unroll
                for (int nt = 0; nt < 16; nt++) {
                    uint4 B = gb[nt * 32];
                    mma16816(c[nt], ahi[0], ahi[1], ahi[2], ahi[3], B.x, B.y);
                    mma16816(c[nt], ahi[0], ahi[1], ahi[2], ahi[3], B.z, B.w);
                    mma16816(c[nt], alo[0], alo[1], alo[2], alo[3], B.x, B.y);
                }
            }
        }

        // ======== feat/sigma GEMM: cf[3][4] = h2 @ [Wf|Wd|0] ========
        float cf[3][4];
#pragma unroll
        for (int nt = 0; nt < 3; nt++)
#pragma unroll
            for (int i = 0; i < 4; i++) cf[nt][i] = 0.f;
#pragma unroll 1
        for (int ks = 0; ks < 8; ks++) {
            int col = ks * 16 + kq;
            float b20 = wsm[512 + col], b21 = wsm[512 + col + 1];
            float b28 = wsm[512 + col + 8], b29 = wsm[512 + col + 9];
            u32 ahi[4], alo[4];
            split_pack(fmaxf(c[2 * ks][0] + b20, 0.f), fmaxf(c[2 * ks][1] + b21, 0.f),
                       ahi[0], alo[0]);
            split_pack(fmaxf(c[2 * ks][2] + b20, 0.f), fmaxf(c[2 * ks][3] + b21, 0.f),
                       ahi[1], alo[1]);
            split_pack(fmaxf(c[2 * ks + 1][0] + b28, 0.f),
                       fmaxf(c[2 * ks + 1][1] + b29, 0.f), ahi[2], alo[2]);
            split_pack(fmaxf(c[2 * ks + 1][2] + b28, 0.f),
                       fmaxf(c[2 * ks + 1][3] + b29, 0.f), ahi[3], alo[3]);
            const uint4* gb = sB + 4096 + ks * 3 * 32 + lane;
#pragma unroll
            for (int nt = 0; nt < 3; nt++) {
                uint4 B = gb[nt * 32];
                mma16816(cf[nt], ahi[0], ahi[1], ahi[2], ahi[3], B.x, B.y);
                mma16816(cf[nt], ahi[0], ahi[1], ahi[2], ahi[3], B.z, B.w);
                mma16816(cf[nt], alo[0], alo[1], alo[2], alo[3], B.x, B.y);
            }
        }
        if ((lane & 3) == 0) {
            float bdv = wsm[784];
            ssig[p0] = expf(cf[2][0] + bdv) * sins[p0];
            ssig[p1] = expf(cf[2][2] + bdv) * sins[p1];
        }

        // ======== c1 GEMM (feat rows): cc[16][4] = feat @ Wc1_f, K=16 ========
        u32 fhi[4], flo[4];
        {
            float bf0 = wsm[768 + kq], bf1 = wsm[768 + kq + 1];
            float bf8 = wsm[768 + kq + 8], bf9 = wsm[768 + kq + 9];
            split_pack(cf[0][0] + bf0, cf[0][1] + bf1, fhi[0], flo[0]);
            split_pack(cf[0][2] + bf0, cf[0][3] + bf1, fhi[1], flo[1]);
            split_pack(cf[1][0] + bf8, cf[1][1] + bf9, fhi[2], flo[2]);
            split_pack(cf[1][2] + bf8, cf[1][3] + bf9, fhi[3], flo[3]);
        }
        float cc[16][4];
#pragma unroll
        for (int nt = 0; nt < 16; nt++)
#pragma unroll
            for (int i = 0; i < 4; i++) cc[nt][i] = 0.f;
#pragma unroll 1
        for (int nt = 0; nt < 16; nt++) {
            uint4 Bf = sB[4864 + nt * 32 + lane];
            mma16816(cc[nt], fhi[0], fhi[1], fhi[2], fhi[3], Bf.x, Bf.y);
            mma16816(cc[nt], fhi[0], fhi[1], fhi[2], fhi[3], Bf.z, Bf.w);
            mma16816(cc[nt], flo[0], flo[1], flo[2], flo[3], Bf.x, Bf.y);
        }

        // ======== c2 GEMM: ccol = relu(cc + bc1 + hcY) @ [Wc2|0] ========
        float ccol[4] = {0.f, 0.f, 0.f, 0.f};
#pragma unroll 1
        for (int ks = 0; ks < 8; ks++) {
            int col = ks * 16 + kq;
            float bb0 = wsm[640 + col] + shcY[col];
            float bb1 = wsm[640 + col + 1] + shcY[col + 1];
            float bb8 = wsm[640 + col + 8] + shcY[col + 8];
            float bb9 = wsm[640 + col + 9] + shcY[col + 9];
            u32 ahi[4], alo[4];
            split_pack(fmaxf(cc[2 * ks][0] + bb0, 0.f), fmaxf(cc[2 * ks][1] + bb1, 0.f),
                       ahi[0], alo[0]);
            split_pack(fmaxf(cc[2 * ks][2] + bb0, 0.f), fmaxf(cc[2 * ks][3] + bb1, 0.f),
                       ahi[1], alo[1]);
            split_pack(fmaxf(cc[2 * ks + 1][0] + bb8, 0.f),
                       fmaxf(cc[2 * ks + 1][1] + bb9, 0.f), ahi[2], alo[2]);
            split_pack(fmaxf(cc[2 * ks + 1][2] + bb8, 0.f),
                       fmaxf(cc[2 * ks + 1][3] + bb9, 0.f), ahi[3], alo[3]);
            uint4 B = sB[5376 + ks * 32 + lane];
            mma16816(ccol, ahi[0], ahi[1], ahi[2], ahi[3], B.x, B.y);
            mma16816(ccol, ahi[0], ahi[1], ahi[2], ahi[3], B.z, B.w);
            mma16816(ccol, alo[0], alo[1], alo[2], alo[3], B.x, B.y);
        }
        {
            int cq = lane & 3;
            if (cq == 0) {
                float b0v = wsm[785], b1v = wsm[786];
                sc0[p0] = 1.f / (1.f + expf(-(ccol[0] + b0v)));
                sc1[p0] = 1.f / (1.f + expf(-(ccol[1] + b1v)));
                sc0[p1] = 1.f / (1.f + expf(-(ccol[2] + b0v)));
                sc1[p1] = 1.f / (1.f + expf(-(ccol[3] + b1v)));
            } else if (cq == 1) {
                float b2v = wsm[787];
                sc2[p0] = 1.f / (1.f + expf(-(ccol[0] + b2v)));
                sc2[p1] = 1.f / (1.f + expf(-(ccol[2] + b2v)));
            }
        }
        __syncthreads();  // (2) ssig, sc0-2 visible

        // ======== integration ========
        float tau = 0.f, tcur = 0.f, sc = 0.f;
        if (wid < 2) {
            tcur = sts[tid];
            float tnext = (tid < 63) ? sts[tid + 1] : (tf + 1.0f);  // BOOSTER = 1.0
            tau = ssig[tid] * (tnext - tcur) * dnorm;
            sc = tau;
#pragma unroll
            for (int off = 1; off < 32; off <<= 1) {
                float u = __shfl_up_sync(0xffffffffu, sc, off);
                if (lane >= off) sc += u;
            }
            if (wid == 0 && lane == 31) sred[15] = sc;
        }
        __syncthreads();  // (3)
        if (wid < 2) {
            if (wid == 1) sc += sred[15];
            float excl = sc - tau;
            float wgt = expf(-excl) * (1.f - expf(-tau));
            float v0 = wgt * sc0[tid];
            float v1 = wgt * sc1[tid];
            float v2 = wgt * sc2[tid];
            float v3 = wgt;
            float v4 = wgt * tcur;
#pragma unroll
            for (int off = 16; off >= 1; off >>= 1) {
                v0 += __shfl_xor_sync(0xffffffffu, v0, off);
                v1 += __shfl_xor_sync(0xffffffffu, v1, off);
                v2 += __shfl_xor_sync(0xffffffffu, v2, off);
                v3 += __shfl_xor_sync(0xffffffffu, v3, off);
                v4 += __shfl_xor_sync(0xffffffffu, v4, off);
            }
            if (lane == 0) {
                sred[wid * 5 + 0] = v0;
                sred[wid * 5 + 1] = v1;
                sred[wid * 5 + 2] = v2;
                sred[wid * 5 + 3] = v3;
                sred[wid * 5 + 4] = v4;
            }
        }
        __syncthreads();  // (4)
        if (tid < 5) {
            float am = active ? 1.f : 0.f;
            out[ray * 5 + tid] = (sred[tid] + sred[5 + tid]) * am;
        }
        __syncthreads();  // (5) protect reused buffers before next iteration
    }
}

extern "C" void kernel_launch(void* const* d_in, const int* in_sizes, int n_in,
                              void* d_out, int out_size) {
    const float* rays_o = (const float*)d_in[0];
    const float* rays_d = (const float*)d_in[1];
    const float* aabb   = (const float*)d_in[2];
    const float* W1  = (const float*)d_in[3];
    const float* b1  = (const float*)d_in[4];
    const float* W2  = (const float*)d_in[5];
    const float* b2  = (const float*)d_in[6];
    const float* Wd  = (const float*)d_in[7];
    const float* bd  = (const float*)d_in[8];
    const float* Wf  = (const float*)d_in[9];
    const float* bf  = (const float*)d_in[10];
    const float* Wc1 = (const float*)d_in[11];
    const float* bc1 = (const float*)d_in[12];
    const float* Wc2 = (const float*)d_in[13];
    const float* bc2 = (const float*)d_in[14];
    float* out = (float*)d_out;

    prep_all<<<192, 32>>>(W2, Wf, Wd, Wc1, Wc2);
    size_t smem = 26112 * sizeof(float);  // 104448 B -> 2 blocks/SM
    cudaFuncSetAttribute(radiance_kernel, cudaFuncAttributeMaxDynamicSharedMemorySize,
                         (int)smem);
    radiance_kernel<<<GRID, 128, smem>>>(rays_o, rays_d, aabb, W1, b1, W2, b2, Wd, bd,
                                         Wf, bf, Wc1, bc1, Wc2, bc2, out);
}

// round 11
// speedup vs baseline: 1.7047x; 1.7047x over previous
#include <cuda_runtime.h>
#include <cuda_bf16.h>
#include <cstdint>

// ----------------------------------------------------------------------------
// RadianceRenderer R11: persistent blocks + smem fragment bank (R10) with the
// HMMA chain restructured into N-halves so accumulator live range is 32 regs
// (c[8][4] / cc[8][4]) -> no register spills (R8-R10's hidden L2 traffic).
// Grid = 296, block = 128 threads, 1 ray/iter, ~28 rays/block.
// ----------------------------------------------------------------------------

typedef unsigned long long ull;
typedef unsigned int u32;

#define GRID 296
#define N_RAYS 8192

// fragment-ordered B operands in GLOBAL (verified R7/R8 packing):
// uint4 = {hi(k0,k0+1), hi(k0+8,k0+9), lo.., lo..}; [tile][lane].
// W2 @0 (128), feat @4096 (24), c1 @4864 (32: 0-15 feat rows, 16-31 ynm), c2 @5888 (8).
__device__ __align__(16) uint4 g_Bf[6144];

__device__ __forceinline__ void cpa16(u32 dst, const void* src) {
    asm volatile("cp.async.ca.shared.global [%0], [%1], 16;" :: "r"(dst), "l"(src));
}
__device__ __forceinline__ void cpa_commit() {
    asm volatile("cp.async.commit_group;" ::: "memory");
}
template <int N>
__device__ __forceinline__ void cpa_wait() {
    asm volatile("cp.async.wait_group %0;" :: "n"(N) : "memory");
}
__device__ __forceinline__ u32 smem_u32(const void* p) {
    return (u32)__cvta_generic_to_shared(p);
}

__device__ __forceinline__ void mma16816(float c[4], u32 a0, u32 a1, u32 a2, u32 a3,
                                         u32 b0, u32 b1) {
    asm volatile(
        "mma.sync.aligned.m16n8k16.row.col.f32.bf16.bf16.f32 "
        "{%0,%1,%2,%3}, {%4,%5,%6,%7}, {%8,%9}, {%0,%1,%2,%3};"
        : "+f"(c[0]), "+f"(c[1]), "+f"(c[2]), "+f"(c[3])
        : "r"(a0), "r"(a1), "r"(a2), "r"(a3), "r"(b0), "r"(b1));
}

__device__ __forceinline__ void split_pack(float v0, float v1, u32& hi, u32& lo) {
    __nv_bfloat16 h0 = __float2bfloat16(v0), h1 = __float2bfloat16(v1);
    hi = (u32)__bfloat16_as_ushort(h0) | ((u32)__bfloat16_as_ushort(h1) << 16);
    __nv_bfloat16 l0 = __float2bfloat16(v0 - __bfloat162float(h0));
    __nv_bfloat16 l1 = __float2bfloat16(v1 - __bfloat162float(h1));
    lo = (u32)__bfloat16_as_ushort(l0) | ((u32)__bfloat16_as_ushort(l1) << 16);
}

// ---------- prep: pack all B operands fragment-ordered (verified) ----------
__global__ void prep_all(const float* __restrict__ W2, const float* __restrict__ Wf,
                         const float* __restrict__ Wd, const float* __restrict__ Wc1,
                         const float* __restrict__ Wc2) {
    int b = blockIdx.x;
    int lane = threadIdx.x;
    int kq = (lane & 3) * 2, nq = lane >> 2;
    float x0, x1, x2, x3;
    uint4* dst;
    if (b < 128) {
        int ks = b >> 4, nt = b & 15;
        int k0 = ks * 16 + kq, n = nt * 8 + nq;
        x0 = W2[k0 * 128 + n];
        x1 = W2[(k0 + 1) * 128 + n];
        x2 = W2[(k0 + 8) * 128 + n];
        x3 = W2[(k0 + 9) * 128 + n];
        dst = g_Bf + b * 32 + lane;
    } else if (b < 152) {
        int idx = b - 128, ks = idx / 3, nt = idx - ks * 3;
        int k0 = ks * 16 + kq, n = nt * 8 + nq;
        auto val = [&](int k) -> float {
            if (n < 16) return Wf[k * 16 + n];
            if (n == 16) return Wd[k];
            return 0.f;
        };
        x0 = val(k0); x1 = val(k0 + 1); x2 = val(k0 + 8); x3 = val(k0 + 9);
        dst = g_Bf + 4096 + idx * 32 + lane;
    } else if (b < 184) {
        int idx = b - 152, ks = idx >> 4, nt = idx & 15;
        int k0 = ks * 16 + kq, n = nt * 8 + nq;
        x0 = Wc1[k0 * 128 + n];
        x1 = Wc1[(k0 + 1) * 128 + n];
        x2 = Wc1[(k0 + 8) * 128 + n];
        x3 = Wc1[(k0 + 9) * 128 + n];
        dst = g_Bf + 4864 + idx * 32 + lane;
    } else {
        int ks = b - 184;
        int k0 = ks * 16 + kq, n = nq;
        auto val = [&](int k) -> float { return (n < 3) ? Wc2[k * 3 + n] : 0.f; };
        x0 = val(k0); x1 = val(k0 + 1); x2 = val(k0 + 8); x3 = val(k0 + 9);
        dst = g_Bf + 5888 + ks * 32 + lane;
    }
    uint4 v;
    split_pack(x0, x1, v.x, v.z);
    split_pack(x2, x3, v.y, v.w);
    *dst = v;
}

// smem floats: sB uint4 [0,22528)=90112B; wsm 22528..23328; wy 23328..25376;
// sxyz 25376(192) sts 25568 ssig 25632 sins 25696 synm 25760(16)
// sc0 25776 sc1 25840 sc2 25904 sred 25968(16) shcY 25984(128). 26112 fl.
__global__ __launch_bounds__(128, 2) void radiance_kernel(
    const float* __restrict__ rays_o, const float* __restrict__ rays_d,
    const float* __restrict__ aabb,
    const float* __restrict__ W1, const float* __restrict__ b1,
    const float* __restrict__ W2, const float* __restrict__ b2,
    const float* __restrict__ Wd, const float* __restrict__ bd,
    const float* __restrict__ Wf, const float* __restrict__ bf,
    const float* __restrict__ Wc1, const float* __restrict__ bc1,
    const float* __restrict__ Wc2, const float* __restrict__ bc2,
    float* __restrict__ out) {
    extern __shared__ float sm[];
    const uint4* sB = (const uint4*)sm;
    float* wsm  = sm + 22528;
    float* wy   = sm + 23328;
    float* sxyz = sm + 25376;
    float* sts  = sm + 25568;
    float* ssig = sm + 25632;
    float* sins = sm + 25696;
    float* synm = sm + 25760;
    float* sc0  = sm + 25776;
    float* sc1  = sm + 25840;
    float* sc2  = sm + 25904;
    float* sred = sm + 25968;
    float* shcY = sm + 25984;

    const int tid = threadIdx.x;
    const int lane = tid & 31;
    const int wid = tid >> 5;
    const int pb = wid * 16;
    const int r0 = lane >> 2;
    const int p0 = pb + r0, p1 = p0 + 8;
    const int kq = (lane & 3) * 2;
    const u32 sBu = smem_u32(sm);

    // ---- one-time staging ----
    {
#pragma unroll
        for (int i = 0; i < 32; i++)
            cpa16(sBu + (u32)(tid + i * 128) * 16u, g_Bf + tid + i * 128);
#pragma unroll
        for (int i = 0; i < 6; i++)
            cpa16(sBu + (u32)(4096 + tid + i * 128) * 16u, g_Bf + 4096 + tid + i * 128);
#pragma unroll
        for (int i = 0; i < 4; i++)
            cpa16(sBu + (u32)(4864 + tid + i * 128) * 16u, g_Bf + 4864 + tid + i * 128);
#pragma unroll
        for (int i = 0; i < 2; i++)
            cpa16(sBu + (u32)(5376 + tid + i * 128) * 16u, g_Bf + 5888 + tid + i * 128);
        u32 wu = smem_u32(wsm);
        if (tid < 96) cpa16(wu + tid * 16u, W1 + tid * 4);
        else cpa16(wu + 1536u + (tid - 96) * 16u, b1 + (tid - 96) * 4);
        if (tid < 32) cpa16(wu + 2048u + tid * 16u, b2 + tid * 4);
        else if (tid < 64) cpa16(wu + 2560u + (tid - 32) * 16u, bc1 + (tid - 32) * 4);
        else if (tid < 68) cpa16(wu + 3072u + (tid - 64) * 16u, bf + (tid - 64) * 4);
        u32 wyu = smem_u32(wy);
#pragma unroll
        for (int i = 0; i < 4; i++)
            cpa16(wyu + (u32)(tid + i * 128) * 16u, Wc1 + 2048 + (tid + i * 128) * 4);
        cpa_commit();
        if (tid == 68) wsm[784] = __ldg(bd);
        if (tid >= 69 && tid < 72) wsm[785 + tid - 69] = __ldg(bc2 + tid - 69);
    }
    float a0x = aabb[0], a0y = aabb[1], a0z = aabb[2];
    float a1x = aabb[3], a1y = aabb[4], a1z = aabb[5];
    cpa_wait<0>();
    __syncthreads();

    // ================= per-ray loop =================
#pragma unroll 1
    for (int ray = blockIdx.x; ray < N_RAYS; ray += GRID) {
        float ox = rays_o[ray * 3 + 0], oy = rays_o[ray * 3 + 1], oz = rays_o[ray * 3 + 2];
        float dx = rays_d[ray * 3 + 0], dy = rays_d[ray * 3 + 1], dz = rays_d[ray * 3 + 2];
        float ix = 1.f / dx, iy = 1.f / dy, iz = 1.f / dz;
        float t1x = (a0x - ox) * ix, t2x = (a1x - ox) * ix;
        float t1y = (a0y - oy) * iy, t2y = (a1y - oy) * iy;
        float t1z = (a0z - oz) * iz, t2z = (a1z - oz) * iz;
        float tn = fmaxf(fmaxf(fminf(t1x, t2x), fminf(t1y, t2y)), fminf(t1z, t2z));
        tn = fmaxf(tn, 0.f);
        float tf = fminf(fminf(fmaxf(t1x, t2x), fmaxf(t1y, t2y)), fmaxf(t1z, t2z));
        tf = fminf(tf, 10.f);
        bool active = tn < tf;
        if (!active) { tn = 0.f; tf = 1.f; }
        float dnorm = sqrtf(dx * dx + dy * dy + dz * dz);

        if (tid == 0) {
            float inv = 1.f / dnorm;
            float x = dx * inv, y = dy * inv, z = dz * inv;
            float x2 = x * x, y2 = y * y, z2 = z * z;
            synm[0]  = 0.282094791773878f;
            synm[1]  = -0.488602511902920f * y;
            synm[2]  = 0.488602511902920f * z;
            synm[3]  = -0.488602511902920f * x;
            synm[4]  = 1.092548430592079f * x * y;
            synm[5]  = -1.092548430592079f * y * z;
            synm[6]  = 0.315391565252520f * (3.0f * z2 - 1.0f);
            synm[7]  = -1.092548430592079f * x * z;
            synm[8]  = 0.546274215296040f * (x2 - y2);
            synm[9]  = -0.590043589926644f * y * (3.0f * x2 - y2);
            synm[10] = 2.890611442640554f * x * y * z;
            synm[11] = -0.457045799464466f * y * (5.0f * z2 - 1.0f);
            synm[12] = 0.373176332590115f * z * (5.0f * z2 - 3.0f);
            synm[13] = -0.457045799464466f * x * (5.0f * z2 - 1.0f);
            synm[14] = 1.445305721320277f * z * (x2 - y2);
            synm[15] = -0.590043589926644f * x * (x2 - 3.0f * y2);
        }
        if (tid < 64) {
            float fr = (tid + 0.5f) * (1.f / 64.f);
            float t = tn + fr * (tf - tn);
            sts[tid] = t;
            float px = fmaf(dx, t, ox), py = fmaf(dy, t, oy), pz = fmaf(dz, t, oz);
            float nx = (px - a0x) / (a1x - a0x) * 2.f - 1.f;
            float ny = (py - a0y) / (a1y - a0y) * 2.f - 1.f;
            float nz = (pz - a0z) / (a1z - a0z) * 2.f - 1.f;
            sxyz[tid * 3 + 0] = nx;
            sxyz[tid * 3 + 1] = ny;
            sxyz[tid * 3 + 2] = nz;
            bool inside = (nx >= -1.f) && (nx <= 1.f) && (ny >= -1.f) && (ny <= 1.f) &&
                          (nz >= -1.f) && (nz <= 1.f);
            sins[tid] = inside ? 1.f : 0.f;
        }
        __syncthreads();  // (1)

        // hcY: point-invariant ynm @ Wc1 (smem)
        {
            float acc = 0.f;
#pragma unroll
            for (int j = 0; j < 16; j++)
                acc = fmaf(synm[j], wy[j * 128 + tid], acc);
            shcY[tid] = acc;
        }

        float P0x = sxyz[p0 * 3], P0y = sxyz[p0 * 3 + 1], P0z = sxyz[p0 * 3 + 2];
        float P1x = sxyz[p1 * 3], P1y = sxyz[p1 * 3 + 1], P1z = sxyz[p1 * 3 + 2];

        // ======== W2 + feat chained in two N-halves (c[8][4] live max) ========
        float cf[3][4];
#pragma unroll
        for (int nt = 0; nt < 3; nt++)
#pragma unroll
            for (int i = 0; i < 4; i++) cf[nt][i] = 0.f;

#pragma unroll 1
        for (int h = 0; h < 2; h++) {
            float c[8][4];
#pragma unroll
            for (int nt = 0; nt < 8; nt++)
#pragma unroll
                for (int i = 0; i < 4; i++) c[nt][i] = 0.f;
            // W2: all K, N-half h
#pragma unroll 1
            for (int ks = 0; ks < 8; ks++) {
                int j0 = ks * 16 + kq;
                float v[8];
#pragma unroll
                for (int q = 0; q < 4; q++) {
                    int j = j0 + (q & 1) + (q >> 1) * 8;
                    float w0 = wsm[j], w1 = wsm[128 + j], w2 = wsm[256 + j];
                    float bb = wsm[384 + j];
                    float h0 = fmaf(P0x, w0, bb);
                    h0 = fmaf(P0y, w1, h0);
                    h0 = fmaf(P0z, w2, h0);
                    float h1v = fmaf(P1x, w0, bb);
                    h1v = fmaf(P1y, w1, h1v);
                    h1v = fmaf(P1z, w2, h1v);
                    v[q] = fmaxf(h0, 0.f);
                    v[4 + q] = fmaxf(h1v, 0.f);
                }
                u32 ahi[4], alo[4];
                split_pack(v[0], v[1], ahi[0], alo[0]);
                split_pack(v[4], v[5], ahi[1], alo[1]);
                split_pack(v[2], v[3], ahi[2], alo[2]);
                split_pack(v[6], v[7], ahi[3], alo[3]);
                const uint4* gb = sB + (ks * 16 + h * 8) * 32 + lane;
#pragma unroll
                for (int nt = 0; nt < 8; nt++) {
                    uint4 B = gb[nt * 32];
                    mma16816(c[nt], ahi[0], ahi[1], ahi[2], ahi[3], B.x, B.y);
                    mma16816(c[nt], ahi[0], ahi[1], ahi[2], ahi[3], B.z, B.w);
                    mma16816(c[nt], alo[0], alo[1], alo[2], alo[3], B.x, B.y);
                }
            }
            // feat: consume this half's h2 cols as k-chunks h*4..h*4+3
#pragma unroll 1
            for (int q = 0; q < 4; q++) {
                int ksf = h * 4 + q;
                int col = ksf * 16 + kq;
                float b20 = wsm[512 + col], b21 = wsm[512 + col + 1];
                float b28 = wsm[512 + col + 8], b29 = wsm[512 + col + 9];
                u32 ahi[4], alo[4];
                split_pack(fmaxf(c[2 * q][0] + b20, 0.f), fmaxf(c[2 * q][1] + b21, 0.f),
                           ahi[0], alo[0]);
                split_pack(fmaxf(c[2 * q][2] + b20, 0.f), fmaxf(c[2 * q][3] + b21, 0.f),
                           ahi[1], alo[1]);
                split_pack(fmaxf(c[2 * q + 1][0] + b28, 0.f),
                           fmaxf(c[2 * q + 1][1] + b29, 0.f), ahi[2], alo[2]);
                split_pack(fmaxf(c[2 * q + 1][2] + b28, 0.f),
                           fmaxf(c[2 * q + 1][3] + b29, 0.f), ahi[3], alo[3]);
                const uint4* gb = sB + 4096 + ksf * 3 * 32 + lane;
#pragma unroll
                for (int nt = 0; nt < 3; nt++) {
                    uint4 B = gb[nt * 32];
                    mma16816(cf[nt], ahi[0], ahi[1], ahi[2], ahi[3], B.x, B.y);
                    mma16816(cf[nt], ahi[0], ahi[1], ahi[2], ahi[3], B.z, B.w);
                    mma16816(cf[nt], alo[0], alo[1], alo[2], alo[3], B.x, B.y);
                }
            }
        }
        if ((lane & 3) == 0) {
            float bdv = wsm[784];
            ssig[p0] = expf(cf[2][0] + bdv) * sins[p0];
            ssig[p1] = expf(cf[2][2] + bdv) * sins[p1];
        }

        // feat A-fragments for c1 (K=16, one chunk)
        u32 fhi[4], flo[4];
        {
            float bf0 = wsm[768 + kq], bf1 = wsm[768 + kq + 1];
            float bf8 = wsm[768 + kq + 8], bf9 = wsm[768 + kq + 9];
            split_pack(cf[0][0] + bf0, cf[0][1] + bf1, fhi[0], flo[0]);
            split_pack(cf[0][2] + bf0, cf[0][3] + bf1, fhi[1], flo[1]);
            split_pack(cf[1][0] + bf8, cf[1][1] + bf9, fhi[2], flo[2]);
            split_pack(cf[1][2] + bf8, cf[1][3] + bf9, fhi[3], flo[3]);
        }

        // ======== c1 + c2 chained in two N-halves (cc[8][4] live max) ========
        float ccol[4] = {0.f, 0.f, 0.f, 0.f};
#pragma unroll 1
        for (int h = 0; h < 2; h++) {
            float cc[8][4];
#pragma unroll
            for (int nt = 0; nt < 8; nt++)
#pragma unroll
                for (int i = 0; i < 4; i++) cc[nt][i] = 0.f;
#pragma unroll
            for (int nt = 0; nt < 8; nt++) {
                uint4 Bf = sB[4864 + (h * 8 + nt) * 32 + lane];
                mma16816(cc[nt], fhi[0], fhi[1], fhi[2], fhi[3], Bf.x, Bf.y);
                mma16816(cc[nt], fhi[0], fhi[1], fhi[2], fhi[3], Bf.z, Bf.w);
                mma16816(cc[nt], flo[0], flo[1], flo[2], flo[3], Bf.x, Bf.y);
            }
#pragma unroll 1
            for (int q = 0; q < 4; q++) {
                int ksc = h * 4 + q;
                int col = ksc * 16 + kq;
                float bb0 = wsm[640 + col] + shcY[col];
                float bb1 = wsm[640 + col + 1] + shcY[col + 1];
                float bb8 = wsm[640 + col + 8] + shcY[col + 8];
                float bb9 = wsm[640 + col + 9] + shcY[col + 9];
                u32 ahi[4], alo[4];
                split_pack(fmaxf(cc[2 * q][0] + bb0, 0.f), fmaxf(cc[2 * q][1] + bb1, 0.f),
                           ahi[0], alo[0]);
                split_pack(fmaxf(cc[2 * q][2] + bb0, 0.f), fmaxf(cc[2 * q][3] + bb1, 0.f),
                           ahi[1], alo[1]);
                split_pack(fmaxf(cc[2 * q + 1][0] + bb8, 0.f),
                           fmaxf(cc[2 * q + 1][1] + bb9, 0.f), ahi[2], alo[2]);
                split_pack(fmaxf(cc[2 * q + 1][2] + bb8, 0.f),
                           fmaxf(cc[2 * q + 1][3] + bb9, 0.f), ahi[3], alo[3]);
                uint4 B = sB[5376 + ksc * 32 + lane];
                mma16816(ccol, ahi[0], ahi[1], ahi[2], ahi[3], B.x, B.y);
                mma16816(ccol, ahi[0], ahi[1], ahi[2], ahi[3], B.z, B.w);
                mma16816(ccol, alo[0], alo[1], alo[2], alo[3], B.x, B.y);
            }
        }
        {
            int cq = lane & 3;
            if (cq == 0) {
                float b0v = wsm[785], b1v = wsm[786];
                sc0[p0] = 1.f / (1.f + expf(-(ccol[0] + b0v)));
                sc1[p0] = 1.f / (1.f + expf(-(ccol[1] + b1v)));
                sc0[p1] = 1.f / (1.f + expf(-(ccol[2] + b0v)));
                sc1[p1] = 1.f / (1.f + expf(-(ccol[3] + b1v)));
            } else if (cq == 1) {
                float b2v = wsm[787];
                sc2[p0] = 1.f / (1.f + expf(-(ccol[0] + b2v)));
                sc2[p1] = 1.f / (1.f + expf(-(ccol[2] + b2v)));
            }
        }
        __syncthreads();  // (2)

        // ======== integration ========
        float tau = 0.f, tcur = 0.f, sc = 0.f;
        if (wid < 2) {
            tcur = sts[tid];
            float tnext = (tid < 63) ? sts[tid + 1] : (tf + 1.0f);  // BOOSTER = 1.0
            tau = ssig[tid] * (tnext - tcur) * dnorm;
            sc = tau;
#pragma unroll
            for (int off = 1; off < 32; off <<= 1) {
                float u = __shfl_up_sync(0xffffffffu, sc, off);
                if (lane >= off) sc += u;
            }
            if (wid == 0 && lane == 31) sred[15] = sc;
        }
        __syncthreads();  // (3)
        if (wid < 2) {
            if (wid == 1) sc += sred[15];
            float excl = sc - tau;
            float wgt = expf(-excl) * (1.f - expf(-tau));
            float v0 = wgt * sc0[tid];
            float v1 = wgt * sc1[tid];
            float v2 = wgt * sc2[tid];
            float v3 = wgt;
            float v4 = wgt * tcur;
#pragma unroll
            for (int off = 16; off >= 1; off >>= 1) {
                v0 += __shfl_xor_sync(0xffffffffu, v0, off);
                v1 += __shfl_xor_sync(0xffffffffu, v1, off);
                v2 += __shfl_xor_sync(0xffffffffu, v2, off);
                v3 += __shfl_xor_sync(0xffffffffu, v3, off);
                v4 += __shfl_xor_sync(0xffffffffu, v4, off);
            }
            if (lane == 0) {
                sred[wid * 5 + 0] = v0;
                sred[wid * 5 + 1] = v1;
                sred[wid * 5 + 2] = v2;
                sred[wid * 5 + 3] = v3;
                sred[wid * 5 + 4] = v4;
            }
        }
        __syncthreads();  // (4)
        if (tid < 5) {
            float am = active ? 1.f : 0.f;
            out[ray * 5 + tid] = (sred[tid] + sred[5 + tid]) * am;
        }
        __syncthreads();  // (5)
    }
}

extern "C" void kernel_launch(void* const* d_in, const int* in_sizes, int n_in,
                              void* d_out, int out_size) {
    const float* rays_o = (const float*)d_in[0];
    const float* rays_d = (const float*)d_in[1];
    const float* aabb   = (const float*)d_in[2];
    const float* W1  = (const float*)d_in[3];
    const float* b1  = (const float*)d_in[4];
    const float* W2  = (const float*)d_in[5];
    const float* b2  = (const float*)d_in[6];
    const float* Wd  = (const float*)d_in[7];
    const float* bd  = (const float*)d_in[8];
    const float* Wf  = (const float*)d_in[9];
    const float* bf  = (const float*)d_in[10];
    const float* Wc1 = (const float*)d_in[11];
    const float* bc1 = (const float*)d_in[12];
    const float* Wc2 = (const float*)d_in[13];
    const float* bc2 = (const float*)d_in[14];
    float* out = (float*)d_out;

    prep_all<<<192, 32>>>(W2, Wf, Wd, Wc1, Wc2);
    size_t smem = 26112 * sizeof(float);  // 104448 B -> 2 blocks/SM
    cudaFuncSetAttribute(radiance_kernel, cudaFuncAttributeMaxDynamicSharedMemorySize,
                         (int)smem);
    radiance_kernel<<<GRID, 128, smem>>>(rays_o, rays_d, aabb, W1, b1, W2, b2, Wd, bd,
                                         Wf, bf, Wc1, bc1, Wc2, bc2, out);
}

// round 12
// speedup vs baseline: 2.1396x; 1.2552x over previous
#include <cuda_runtime.h>
#include <cuda_bf16.h>
#include <cstdint>

// ----------------------------------------------------------------------------
// RadianceRenderer R12: R11's spill-free chained HMMA MLP, now 256-thread
// blocks processing 2 rays/iteration (warps 0-3 ray A, 4-7 ray B) sharing one
// smem fragment bank -> 16 warps/SM (4/SMSP) at the same smem cost per ray.
// Grid = 296 persistent blocks, ~14 iterations each.
// ----------------------------------------------------------------------------

typedef unsigned long long ull;
typedef unsigned int u32;

#define GRID 296
#define N_PAIRS 4096   // 8192 rays / 2

// fragment-ordered B operands in GLOBAL (verified packing):
// uint4 = {hi(k0,k0+1), hi(k0+8,k0+9), lo.., lo..}; [tile][lane].
// W2 @0 (128), feat @4096 (24), c1 @4864 (32), c2 @5888 (8).
__device__ __align__(16) uint4 g_Bf[6144];

__device__ __forceinline__ void cpa16(u32 dst, const void* src) {
    asm volatile("cp.async.ca.shared.global [%0], [%1], 16;" :: "r"(dst), "l"(src));
}
__device__ __forceinline__ void cpa_commit() {
    asm volatile("cp.async.commit_group;" ::: "memory");
}
template <int N>
__device__ __forceinline__ void cpa_wait() {
    asm volatile("cp.async.wait_group %0;" :: "n"(N) : "memory");
}
__device__ __forceinline__ u32 smem_u32(const void* p) {
    return (u32)__cvta_generic_to_shared(p);
}

__device__ __forceinline__ void mma16816(float c[4], u32 a0, u32 a1, u32 a2, u32 a3,
                                         u32 b0, u32 b1) {
    asm volatile(
        "mma.sync.aligned.m16n8k16.row.col.f32.bf16.bf16.f32 "
        "{%0,%1,%2,%3}, {%4,%5,%6,%7}, {%8,%9}, {%0,%1,%2,%3};"
        : "+f"(c[0]), "+f"(c[1]), "+f"(c[2]), "+f"(c[3])
        : "r"(a0), "r"(a1), "r"(a2), "r"(a3), "r"(b0), "r"(b1));
}

__device__ __forceinline__ void split_pack(float v0, float v1, u32& hi, u32& lo) {
    __nv_bfloat16 h0 = __float2bfloat16(v0), h1 = __float2bfloat16(v1);
    hi = (u32)__bfloat16_as_ushort(h0) | ((u32)__bfloat16_as_ushort(h1) << 16);
    __nv_bfloat16 l0 = __float2bfloat16(v0 - __bfloat162float(h0));
    __nv_bfloat16 l1 = __float2bfloat16(v1 - __bfloat162float(h1));
    lo = (u32)__bfloat16_as_ushort(l0) | ((u32)__bfloat16_as_ushort(l1) << 16);
}

// ---------- prep: pack all B operands fragment-ordered (verified) ----------
__global__ void prep_all(const float* __restrict__ W2, const float* __restrict__ Wf,
                         const float* __restrict__ Wd, const float* __restrict__ Wc1,
                         const float* __restrict__ Wc2) {
    int b = blockIdx.x;
    int lane = threadIdx.x;
    int kq = (lane & 3) * 2, nq = lane >> 2;
    float x0, x1, x2, x3;
    uint4* dst;
    if (b < 128) {
        int ks = b >> 4, nt = b & 15;
        int k0 = ks * 16 + kq, n = nt * 8 + nq;
        x0 = W2[k0 * 128 + n];
        x1 = W2[(k0 + 1) * 128 + n];
        x2 = W2[(k0 + 8) * 128 + n];
        x3 = W2[(k0 + 9) * 128 + n];
        dst = g_Bf + b * 32 + lane;
    } else if (b < 152) {
        int idx = b - 128, ks = idx / 3, nt = idx - ks * 3;
        int k0 = ks * 16 + kq, n = nt * 8 + nq;
        auto val = [&](int k) -> float {
            if (n < 16) return Wf[k * 16 + n];
            if (n == 16) return Wd[k];
            return 0.f;
        };
        x0 = val(k0); x1 = val(k0 + 1); x2 = val(k0 + 8); x3 = val(k0 + 9);
        dst = g_Bf + 4096 + idx * 32 + lane;
    } else if (b < 184) {
        int idx = b - 152, ks = idx >> 4, nt = idx & 15;
        int k0 = ks * 16 + kq, n = nt * 8 + nq;
        x0 = Wc1[k0 * 128 + n];
        x1 = Wc1[(k0 + 1) * 128 + n];
        x2 = Wc1[(k0 + 8) * 128 + n];
        x3 = Wc1[(k0 + 9) * 128 + n];
        dst = g_Bf + 4864 + idx * 32 + lane;
    } else {
        int ks = b - 184;
        int k0 = ks * 16 + kq, n = nq;
        auto val = [&](int k) -> float { return (n < 3) ? Wc2[k * 3 + n] : 0.f; };
        x0 = val(k0); x1 = val(k0 + 1); x2 = val(k0 + 8); x3 = val(k0 + 9);
        dst = g_Bf + 5888 + ks * 32 + lane;
    }
    uint4 v;
    split_pack(x0, x1, v.x, v.z);
    split_pack(x2, x3, v.y, v.w);
    *dst = v;
}

// smem floats: sB uint4 [0,22528)=90112B; wsm 22528..23328; wy 23328..25376;
// per-slot (x2): sxyz 25376(192ea) sts 25760(64) ssig 25888(64) sins 26016(64)
// synm 26144(16) sc0 26176(64) sc1 26304(64) sc2 26432(64) sred 26560(16)
// shcY 26592(128). total 26848 fl = 107392 B -> 2 blocks/SM.
__global__ __launch_bounds__(256, 2) void radiance_kernel(
    const float* __restrict__ rays_o, const float* __restrict__ rays_d,
    const float* __restrict__ aabb,
    const float* __restrict__ W1, const float* __restrict__ b1,
    const float* __restrict__ W2, const float* __restrict__ b2,
    const float* __restrict__ Wd, const float* __restrict__ bd,
    const float* __restrict__ Wf, const float* __restrict__ bf,
    const float* __restrict__ Wc1, const float* __restrict__ bc1,
    const float* __restrict__ Wc2, const float* __restrict__ bc2,
    float* __restrict__ out) {
    extern __shared__ float sm[];
    const uint4* sB = (const uint4*)sm;
    float* wsm = sm + 22528;
    float* wy  = sm + 23328;

    const int tid = threadIdx.x;
    const int lane = tid & 31;
    const int wid = tid >> 5;
    const int slot = tid >> 7;      // 0 or 1 (= wid>>2)
    const int t128 = tid & 127;
    const int lwid = wid & 3;       // warp within slot
    const int pb = lwid * 16;
    const int r0 = lane >> 2;
    const int p0 = pb + r0, p1 = p0 + 8;
    const int kq = (lane & 3) * 2;
    const u32 sBu = smem_u32(sm);

    float* sxyz_s = sm + 25376 + slot * 192;
    float* sts_s  = sm + 25760 + slot * 64;
    float* ssig_s = sm + 25888 + slot * 64;
    float* sins_s = sm + 26016 + slot * 64;
    float* synm_s = sm + 26144 + slot * 16;
    float* sc0_s  = sm + 26176 + slot * 64;
    float* sc1_s  = sm + 26304 + slot * 64;
    float* sc2_s  = sm + 26432 + slot * 64;
    float* sred_s = sm + 26560 + slot * 16;
    float* shcY_s = sm + 26592 + slot * 128;

    // ---- one-time staging (256 threads) ----
    {
#pragma unroll
        for (int i = 0; i < 16; i++)   // W2 fragments (4096 uint4)
            cpa16(sBu + (u32)(tid + i * 256) * 16u, g_Bf + tid + i * 256);
#pragma unroll
        for (int i = 0; i < 3; i++)    // feat (768)
            cpa16(sBu + (u32)(4096 + tid + i * 256) * 16u, g_Bf + 4096 + tid + i * 256);
#pragma unroll
        for (int i = 0; i < 2; i++)    // c1 (512)
            cpa16(sBu + (u32)(4864 + tid + i * 256) * 16u, g_Bf + 4864 + tid + i * 256);
        cpa16(sBu + (u32)(5376 + tid) * 16u, g_Bf + 5888 + tid);  // c2 (256)
        u32 wu = smem_u32(wsm);
        if (tid < 96) cpa16(wu + tid * 16u, W1 + tid * 4);
        else if (tid < 128) cpa16(wu + 1536u + (tid - 96) * 16u, b1 + (tid - 96) * 4);
        else if (tid < 160) cpa16(wu + 2048u + (tid - 128) * 16u, b2 + (tid - 128) * 4);
        else if (tid < 192) cpa16(wu + 2560u + (tid - 160) * 16u, bc1 + (tid - 160) * 4);
        else if (tid < 196) cpa16(wu + 3072u + (tid - 192) * 16u, bf + (tid - 192) * 4);
        u32 wyu = smem_u32(wy);
#pragma unroll
        for (int i = 0; i < 2; i++)    // Wc1 ynm rows (512 cpa)
            cpa16(wyu + (u32)(tid + i * 256) * 16u, Wc1 + 2048 + (tid + i * 256) * 4);
        cpa_commit();
        if (tid == 200) wsm[784] = __ldg(bd);
        if (tid >= 201 && tid < 204) wsm[785 + tid - 201] = __ldg(bc2 + tid - 201);
    }
    float a0x = aabb[0], a0y = aabb[1], a0z = aabb[2];
    float a1x = aabb[3], a1y = aabb[4], a1z = aabb[5];
    cpa_wait<0>();
    __syncthreads();

    // ================= per-ray-pair loop =================
#pragma unroll 1
    for (int pr = blockIdx.x; pr < N_PAIRS; pr += GRID) {
        const int ray = pr * 2 + slot;
        float ox = rays_o[ray * 3 + 0], oy = rays_o[ray * 3 + 1], oz = rays_o[ray * 3 + 2];
        float dx = rays_d[ray * 3 + 0], dy = rays_d[ray * 3 + 1], dz = rays_d[ray * 3 + 2];
        float ix = 1.f / dx, iy = 1.f / dy, iz = 1.f / dz;
        float t1x = (a0x - ox) * ix, t2x = (a1x - ox) * ix;
        float t1y = (a0y - oy) * iy, t2y = (a1y - oy) * iy;
        float t1z = (a0z - oz) * iz, t2z = (a1z - oz) * iz;
        float tn = fmaxf(fmaxf(fminf(t1x, t2x), fminf(t1y, t2y)), fminf(t1z, t2z));
        tn = fmaxf(tn, 0.f);
        float tf = fminf(fminf(fmaxf(t1x, t2x), fmaxf(t1y, t2y)), fmaxf(t1z, t2z));
        tf = fminf(tf, 10.f);
        bool active = tn < tf;
        if (!active) { tn = 0.f; tf = 1.f; }
        float dnorm = sqrtf(dx * dx + dy * dy + dz * dz);

        if (t128 == 0) {
            float inv = 1.f / dnorm;
            float x = dx * inv, y = dy * inv, z = dz * inv;
            float x2 = x * x, y2 = y * y, z2 = z * z;
            synm_s[0]  = 0.282094791773878f;
            synm_s[1]  = -0.488602511902920f * y;
            synm_s[2]  = 0.488602511902920f * z;
            synm_s[3]  = -0.488602511902920f * x;
            synm_s[4]  = 1.092548430592079f * x * y;
            synm_s[5]  = -1.092548430592079f * y * z;
            synm_s[6]  = 0.315391565252520f * (3.0f * z2 - 1.0f);
            synm_s[7]  = -1.092548430592079f * x * z;
            synm_s[8]  = 0.546274215296040f * (x2 - y2);
            synm_s[9]  = -0.590043589926644f * y * (3.0f * x2 - y2);
            synm_s[10] = 2.890611442640554f * x * y * z;
            synm_s[11] = -0.457045799464466f * y * (5.0f * z2 - 1.0f);
            synm_s[12] = 0.373176332590115f * z * (5.0f * z2 - 3.0f);
            synm_s[13] = -0.457045799464466f * x * (5.0f * z2 - 1.0f);
            synm_s[14] = 1.445305721320277f * z * (x2 - y2);
            synm_s[15] = -0.590043589926644f * x * (x2 - 3.0f * y2);
        }
        if (t128 < 64) {
            float fr = (t128 + 0.5f) * (1.f / 64.f);
            float t = tn + fr * (tf - tn);
            sts_s[t128] = t;
            float px = fmaf(dx, t, ox), py = fmaf(dy, t, oy), pz = fmaf(dz, t, oz);
            float nx = (px - a0x) / (a1x - a0x) * 2.f - 1.f;
            float ny = (py - a0y) / (a1y - a0y) * 2.f - 1.f;
            float nz = (pz - a0z) / (a1z - a0z) * 2.f - 1.f;
            sxyz_s[t128 * 3 + 0] = nx;
            sxyz_s[t128 * 3 + 1] = ny;
            sxyz_s[t128 * 3 + 2] = nz;
            bool inside = (nx >= -1.f) && (nx <= 1.f) && (ny >= -1.f) && (ny <= 1.f) &&
                          (nz >= -1.f) && (nz <= 1.f);
            sins_s[t128] = inside ? 1.f : 0.f;
        }
        __syncthreads();  // (1)

        // hcY: point-invariant ynm @ Wc1 (one 128-vector per slot)
        {
            float acc = 0.f;
#pragma unroll
            for (int j = 0; j < 16; j++)
                acc = fmaf(synm_s[j], wy[j * 128 + t128], acc);
            shcY_s[t128] = acc;
        }

        float P0x = sxyz_s[p0 * 3], P0y = sxyz_s[p0 * 3 + 1], P0z = sxyz_s[p0 * 3 + 2];
        float P1x = sxyz_s[p1 * 3], P1y = sxyz_s[p1 * 3 + 1], P1z = sxyz_s[p1 * 3 + 2];

        // ======== W2 + feat chained in two N-halves ========
        float cf[3][4];
#pragma unroll
        for (int nt = 0; nt < 3; nt++)
#pragma unroll
            for (int i = 0; i < 4; i++) cf[nt][i] = 0.f;

#pragma unroll 1
        for (int h = 0; h < 2; h++) {
            float c[8][4];
#pragma unroll
            for (int nt = 0; nt < 8; nt++)
#pragma unroll
                for (int i = 0; i < 4; i++) c[nt][i] = 0.f;
#pragma unroll 1
            for (int ks = 0; ks < 8; ks++) {
                int j0 = ks * 16 + kq;
                float v[8];
#pragma unroll
                for (int q = 0; q < 4; q++) {
                    int j = j0 + (q & 1) + (q >> 1) * 8;
                    float w0 = wsm[j], w1 = wsm[128 + j], w2 = wsm[256 + j];
                    float bb = wsm[384 + j];
                    float h0 = fmaf(P0x, w0, bb);
                    h0 = fmaf(P0y, w1, h0);
                    h0 = fmaf(P0z, w2, h0);
                    float h1v = fmaf(P1x, w0, bb);
                    h1v = fmaf(P1y, w1, h1v);
                    h1v = fmaf(P1z, w2, h1v);
                    v[q] = fmaxf(h0, 0.f);
                    v[4 + q] = fmaxf(h1v, 0.f);
                }
                u32 ahi[4], alo[4];
                split_pack(v[0], v[1], ahi[0], alo[0]);
                split_pack(v[4], v[5], ahi[1], alo[1]);
                split_pack(v[2], v[3], ahi[2], alo[2]);
                split_pack(v[6], v[7], ahi[3], alo[3]);
                const uint4* gb = sB + (ks * 16 + h * 8) * 32 + lane;
#pragma unroll
                for (int nt = 0; nt < 8; nt++) {
                    uint4 B = gb[nt * 32];
                    mma16816(c[nt], ahi[0], ahi[1], ahi[2], ahi[3], B.x, B.y);
                    mma16816(c[nt], ahi[0], ahi[1], ahi[2], ahi[3], B.z, B.w);
                    mma16816(c[nt], alo[0], alo[1], alo[2], alo[3], B.x, B.y);
                }
            }
#pragma unroll 1
            for (int q = 0; q < 4; q++) {
                int ksf = h * 4 + q;
                int col = ksf * 16 + kq;
                float b20 = wsm[512 + col], b21 = wsm[512 + col + 1];
                float b28 = wsm[512 + col + 8], b29 = wsm[512 + col + 9];
                u32 ahi[4], alo[4];
                split_pack(fmaxf(c[2 * q][0] + b20, 0.f), fmaxf(c[2 * q][1] + b21, 0.f),
                           ahi[0], alo[0]);
                split_pack(fmaxf(c[2 * q][2] + b20, 0.f), fmaxf(c[2 * q][3] + b21, 0.f),
                           ahi[1], alo[1]);
                split_pack(fmaxf(c[2 * q + 1][0] + b28, 0.f),
                           fmaxf(c[2 * q + 1][1] + b29, 0.f), ahi[2], alo[2]);
                split_pack(fmaxf(c[2 * q + 1][2] + b28, 0.f),
                           fmaxf(c[2 * q + 1][3] + b29, 0.f), ahi[3], alo[3]);
                const uint4* gb = sB + 4096 + ksf * 3 * 32 + lane;
#pragma unroll
                for (int nt = 0; nt < 3; nt++) {
                    uint4 B = gb[nt * 32];
                    mma16816(cf[nt], ahi[0], ahi[1], ahi[2], ahi[3], B.x, B.y);
                    mma16816(cf[nt], ahi[0], ahi[1], ahi[2], ahi[3], B.z, B.w);
                    mma16816(cf[nt], alo[0], alo[1], alo[2], alo[3], B.x, B.y);
                }
            }
        }
        if ((lane & 3) == 0) {
            float bdv = wsm[784];
            ssig_s[p0] = expf(cf[2][0] + bdv) * sins_s[p0];
            ssig_s[p1] = expf(cf[2][2] + bdv) * sins_s[p1];
        }

        // feat A-fragments for c1 (K=16)
        u32 fhi[4], flo[4];
        {
            float bf0 = wsm[768 + kq], bf1 = wsm[768 + kq + 1];
            float bf8 = wsm[768 + kq + 8], bf9 = wsm[768 + kq + 9];
            split_pack(cf[0][0] + bf0, cf[0][1] + bf1, fhi[0], flo[0]);
            split_pack(cf[0][2] + bf0, cf[0][3] + bf1, fhi[1], flo[1]);
            split_pack(cf[1][0] + bf8, cf[1][1] + bf9, fhi[2], flo[2]);
            split_pack(cf[1][2] + bf8, cf[1][3] + bf9, fhi[3], flo[3]);
        }

        // ======== c1 + c2 chained in two N-halves ========
        float ccol[4] = {0.f, 0.f, 0.f, 0.f};
#pragma unroll 1
        for (int h = 0; h < 2; h++) {
            float cc[8][4];
#pragma unroll
            for (int nt = 0; nt < 8; nt++)
#pragma unroll
                for (int i = 0; i < 4; i++) cc[nt][i] = 0.f;
#pragma unroll
            for (int nt = 0; nt < 8; nt++) {
                uint4 Bf = sB[4864 + (h * 8 + nt) * 32 + lane];
                mma16816(cc[nt], fhi[0], fhi[1], fhi[2], fhi[3], Bf.x, Bf.y);
                mma16816(cc[nt], fhi[0], fhi[1], fhi[2], fhi[3], Bf.z, Bf.w);
                mma16816(cc[nt], flo[0], flo[1], flo[2], flo[3], Bf.x, Bf.y);
            }
#pragma unroll 1
            for (int q = 0; q < 4; q++) {
                int ksc = h * 4 + q;
                int col = ksc * 16 + kq;
                float bb0 = wsm[640 + col] + shcY_s[col];
                float bb1 = wsm[640 + col + 1] + shcY_s[col + 1];
                float bb8 = wsm[640 + col + 8] + shcY_s[col + 8];
                float bb9 = wsm[640 + col + 9] + shcY_s[col + 9];
                u32 ahi[4], alo[4];
                split_pack(fmaxf(cc[2 * q][0] + bb0, 0.f), fmaxf(cc[2 * q][1] + bb1, 0.f),
                           ahi[0], alo[0]);
                split_pack(fmaxf(cc[2 * q][2] + bb0, 0.f), fmaxf(cc[2 * q][3] + bb1, 0.f),
                           ahi[1], alo[1]);
                split_pack(fmaxf(cc[2 * q + 1][0] + bb8, 0.f),
                           fmaxf(cc[2 * q + 1][1] + bb9, 0.f), ahi[2], alo[2]);
                split_pack(fmaxf(cc[2 * q + 1][2] + bb8, 0.f),
                           fmaxf(cc[2 * q + 1][3] + bb9, 0.f), ahi[3], alo[3]);
                uint4 B = sB[5376 + ksc * 32 + lane];
                mma16816(ccol, ahi[0], ahi[1], ahi[2], ahi[3], B.x, B.y);
                mma16816(ccol, ahi[0], ahi[1], ahi[2], ahi[3], B.z, B.w);
                mma16816(ccol, alo[0], alo[1], alo[2], alo[3], B.x, B.y);
            }
        }
        {
            int cq = lane & 3;
            if (cq == 0) {
                float b0v = wsm[785], b1v = wsm[786];
                sc0_s[p0] = 1.f / (1.f + expf(-(ccol[0] + b0v)));
                sc1_s[p0] = 1.f / (1.f + expf(-(ccol[1] + b1v)));
                sc0_s[p1] = 1.f / (1.f + expf(-(ccol[2] + b0v)));
                sc1_s[p1] = 1.f / (1.f + expf(-(ccol[3] + b1v)));
            } else if (cq == 1) {
                float b2v = wsm[787];
                sc2_s[p0] = 1.f / (1.f + expf(-(ccol[0] + b2v)));
                sc2_s[p1] = 1.f / (1.f + expf(-(ccol[2] + b2v)));
            }
        }
        __syncthreads();  // (2)

        // ======== integration (warps lwid 0,1 of each slot) ========
        float tau = 0.f, tcur = 0.f, sc = 0.f;
        if (lwid < 2) {
            tcur = sts_s[t128];
            float tnext = (t128 < 63) ? sts_s[t128 + 1] : (tf + 1.0f);  // BOOSTER=1.0
            tau = ssig_s[t128] * (tnext - tcur) * dnorm;
            sc = tau;
#pragma unroll
            for (int off = 1; off < 32; off <<= 1) {
                float u = __shfl_up_sync(0xffffffffu, sc, off);
                if (lane >= off) sc += u;
            }
            if (lwid == 0 && lane == 31) sred_s[15] = sc;
        }
        __syncthreads();  // (3)
        if (lwid < 2) {
            if (lwid == 1) sc += sred_s[15];
            float excl = sc - tau;
            float wgt = expf(-excl) * (1.f - expf(-tau));
            float v0 = wgt * sc0_s[t128];
            float v1 = wgt * sc1_s[t128];
            float v2 = wgt * sc2_s[t128];
            float v3 = wgt;
            float v4 = wgt * tcur;
#pragma unroll
            for (int off = 16; off >= 1; off >>= 1) {
                v0 += __shfl_xor_sync(0xffffffffu, v0, off);
                v1 += __shfl_xor_sync(0xffffffffu, v1, off);
                v2 += __shfl_xor_sync(0xffffffffu, v2, off);
                v3 += __shfl_xor_sync(0xffffffffu, v3, off);
                v4 += __shfl_xor_sync(0xffffffffu, v4, off);
            }
            if (lane == 0) {
                sred_s[lwid * 5 + 0] = v0;
                sred_s[lwid * 5 + 1] = v1;
                sred_s[lwid * 5 + 2] = v2;
                sred_s[lwid * 5 + 3] = v3;
                sred_s[lwid * 5 + 4] = v4;
            }
        }
        __syncthreads();  // (4)
        if (t128 < 5) {
            float am = active ? 1.f : 0.f;
            out[ray * 5 + t128] = (sred_s[t128] + sred_s[5 + t128]) * am;
        }
        __syncthreads();  // (5) protect reused buffers
    }
}

extern "C" void kernel_launch(void* const* d_in, const int* in_sizes, int n_in,
                              void* d_out, int out_size) {
    const float* rays_o = (const float*)d_in[0];
    const float* rays_d = (const float*)d_in[1];
    const float* aabb   = (const float*)d_in[2];
    const float* W1  = (const float*)d_in[3];
    const float* b1  = (const float*)d_in[4];
    const float* W2  = (const float*)d_in[5];
    const float* b2  = (const float*)d_in[6];
    const float* Wd  = (const float*)d_in[7];
    const float* bd  = (const float*)d_in[8];
    const float* Wf  = (const float*)d_in[9];
    const float* bf  = (const float*)d_in[10];
    const float* Wc1 = (const float*)d_in[11];
    const float* bc1 = (const float*)d_in[12];
    const float* Wc2 = (const float*)d_in[13];
    const float* bc2 = (const float*)d_in[14];
    float* out = (float*)d_out;

    prep_all<<<192, 32>>>(W2, Wf, Wd, Wc1, Wc2);
    size_t smem = 26848 * sizeof(float);  // 107392 B -> 2 blocks/SM
    cudaFuncSetAttribute(radiance_kernel, cudaFuncAttributeMaxDynamicSharedMemorySize,
                         (int)smem);
    radiance_kernel<<<GRID, 256, smem>>>(rays_o, rays_d, aabb, W1, b1, W2, b2, Wd, bd,
                                         Wf, bf, Wc1, bc1, Wc2, bc2, out);
}

// round 13
// speedup vs baseline: 2.7734x; 1.2962x over previous
#include <cuda_runtime.h>
#include <cuda_bf16.h>
#include <cstdint>

// ----------------------------------------------------------------------------
// RadianceRenderer R13: R12 (2 rays/block, persistent, smem fragment bank) with
// (a) consumer loops fully unrolled so accumulator arrays stay in REGISTERS
//     (R11/R12 dynamically indexed them -> silent local-memory demotion), and
// (b) split_pack via packed cvt.rn.bf16x2.f32 (11 -> 6 instructions).
// Grid = 296 persistent blocks, 256 threads, 2 rays/iteration.
// ----------------------------------------------------------------------------

typedef unsigned long long ull;
typedef unsigned int u32;

#define GRID 296
#define N_PAIRS 4096   // 8192 rays / 2

// fragment-ordered B operands in GLOBAL (verified packing):
// uint4 = {hi(k0,k0+1), hi(k0+8,k0+9), lo.., lo..}; [tile][lane].
// W2 @0 (128), feat @4096 (24), c1 @4864 (32), c2 @5888 (8).
__device__ __align__(16) uint4 g_Bf[6144];

__device__ __forceinline__ void cpa16(u32 dst, const void* src) {
    asm volatile("cp.async.ca.shared.global [%0], [%1], 16;" :: "r"(dst), "l"(src));
}
__device__ __forceinline__ void cpa_commit() {
    asm volatile("cp.async.commit_group;" ::: "memory");
}
template <int N>
__device__ __forceinline__ void cpa_wait() {
    asm volatile("cp.async.wait_group %0;" :: "n"(N) : "memory");
}
__device__ __forceinline__ u32 smem_u32(const void* p) {
    return (u32)__cvta_generic_to_shared(p);
}

__device__ __forceinline__ void mma16816(float c[4], u32 a0, u32 a1, u32 a2, u32 a3,
                                         u32 b0, u32 b1) {
    asm volatile(
        "mma.sync.aligned.m16n8k16.row.col.f32.bf16.bf16.f32 "
        "{%0,%1,%2,%3}, {%4,%5,%6,%7}, {%8,%9}, {%0,%1,%2,%3};"
        : "+f"(c[0]), "+f"(c[1]), "+f"(c[2]), "+f"(c[3])
        : "r"(a0), "r"(a1), "r"(a2), "r"(a3), "r"(b0), "r"(b1));
}

// fast split: hi = {bf16(v1)|bf16(v0)}, lo = residuals, via packed cvt
__device__ __forceinline__ void split_pack(float v0, float v1, u32& hi, u32& lo) {
    u32 h;
    asm("cvt.rn.bf16x2.f32 %0, %1, %2;" : "=r"(h) : "f"(v1), "f"(v0));
    float f0 = __uint_as_float(h << 16);
    float f1 = __uint_as_float(h & 0xFFFF0000u);
    u32 l;
    asm("cvt.rn.bf16x2.f32 %0, %1, %2;" : "=r"(l) : "f"(v1 - f1), "f"(v0 - f0));
    hi = h;
    lo = l;
}

// ---------- prep: pack all B operands fragment-ordered (verified) ----------
__global__ void prep_all(const float* __restrict__ W2, const float* __restrict__ Wf,
                         const float* __restrict__ Wd, const float* __restrict__ Wc1,
                         const float* __restrict__ Wc2) {
    int b = blockIdx.x;
    int lane = threadIdx.x;
    int kq = (lane & 3) * 2, nq = lane >> 2;
    float x0, x1, x2, x3;
    uint4* dst;
    if (b < 128) {
        int ks = b >> 4, nt = b & 15;
        int k0 = ks * 16 + kq, n = nt * 8 + nq;
        x0 = W2[k0 * 128 + n];
        x1 = W2[(k0 + 1) * 128 + n];
        x2 = W2[(k0 + 8) * 128 + n];
        x3 = W2[(k0 + 9) * 128 + n];
        dst = g_Bf + b * 32 + lane;
    } else if (b < 152) {
        int idx = b - 128, ks = idx / 3, nt = idx - ks * 3;
        int k0 = ks * 16 + kq, n = nt * 8 + nq;
        auto val = [&](int k) -> float {
            if (n < 16) return Wf[k * 16 + n];
            if (n == 16) return Wd[k];
            return 0.f;
        };
        x0 = val(k0); x1 = val(k0 + 1); x2 = val(k0 + 8); x3 = val(k0 + 9);
        dst = g_Bf + 4096 + idx * 32 + lane;
    } else if (b < 184) {
        int idx = b - 152, ks = idx >> 4, nt = idx & 15;
        int k0 = ks * 16 + kq, n = nt * 8 + nq;
        x0 = Wc1[k0 * 128 + n];
        x1 = Wc1[(k0 + 1) * 128 + n];
        x2 = Wc1[(k0 + 8) * 128 + n];
        x3 = Wc1[(k0 + 9) * 128 + n];
        dst = g_Bf + 4864 + idx * 32 + lane;
    } else {
        int ks = b - 184;
        int k0 = ks * 16 + kq, n = nq;
        auto val = [&](int k) -> float { return (n < 3) ? Wc2[k * 3 + n] : 0.f; };
        x0 = val(k0); x1 = val(k0 + 1); x2 = val(k0 + 8); x3 = val(k0 + 9);
        dst = g_Bf + 5888 + ks * 32 + lane;
    }
    uint4 v;
    split_pack(x0, x1, v.x, v.z);
    split_pack(x2, x3, v.y, v.w);
    *dst = v;
}

// smem floats: sB uint4 [0,22528)=90112B; wsm 22528..23328; wy 23328..25376;
// per-slot (x2): sxyz 25376(192ea) sts 25760(64) ssig 25888(64) sins 26016(64)
// synm 26144(16) sc0 26176(64) sc1 26304(64) sc2 26432(64) sred 26560(16)
// shcY 26592(128). total 26848 fl = 107392 B -> 2 blocks/SM.
__global__ __launch_bounds__(256, 2) void radiance_kernel(
    const float* __restrict__ rays_o, const float* __restrict__ rays_d,
    const float* __restrict__ aabb,
    const float* __restrict__ W1, const float* __restrict__ b1,
    const float* __restrict__ W2, const float* __restrict__ b2,
    const float* __restrict__ Wd, const float* __restrict__ bd,
    const float* __restrict__ Wf, const float* __restrict__ bf,
    const float* __restrict__ Wc1, const float* __restrict__ bc1,
    const float* __restrict__ Wc2, const float* __restrict__ bc2,
    float* __restrict__ out) {
    extern __shared__ float sm[];
    const uint4* sB = (const uint4*)sm;
    float* wsm = sm + 22528;
    float* wy  = sm + 23328;

    const int tid = threadIdx.x;
    const int lane = tid & 31;
    const int wid = tid >> 5;
    const int slot = tid >> 7;
    const int t128 = tid & 127;
    const int lwid = wid & 3;
    const int pb = lwid * 16;
    const int r0 = lane >> 2;
    const int p0 = pb + r0, p1 = p0 + 8;
    const int kq = (lane & 3) * 2;
    const u32 sBu = smem_u32(sm);

    float* sxyz_s = sm + 25376 + slot * 192;
    float* sts_s  = sm + 25760 + slot * 64;
    float* ssig_s = sm + 25888 + slot * 64;
    float* sins_s = sm + 26016 + slot * 64;
    float* synm_s = sm + 26144 + slot * 16;
    float* sc0_s  = sm + 26176 + slot * 64;
    float* sc1_s  = sm + 26304 + slot * 64;
    float* sc2_s  = sm + 26432 + slot * 64;
    float* sred_s = sm + 26560 + slot * 16;
    float* shcY_s = sm + 26592 + slot * 128;

    // ---- one-time staging (256 threads) ----
    {
#pragma unroll
        for (int i = 0; i < 16; i++)
            cpa16(sBu + (u32)(tid + i * 256) * 16u, g_Bf + tid + i * 256);
#pragma unroll
        for (int i = 0; i < 3; i++)
            cpa16(sBu + (u32)(4096 + tid + i * 256) * 16u, g_Bf + 4096 + tid + i * 256);
#pragma unroll
        for (int i = 0; i < 2; i++)
            cpa16(sBu + (u32)(4864 + tid + i * 256) * 16u, g_Bf + 4864 + tid + i * 256);
        cpa16(sBu + (u32)(5376 + tid) * 16u, g_Bf + 5888 + tid);
        u32 wu = smem_u32(wsm);
        if (tid < 96) cpa16(wu + tid * 16u, W1 + tid * 4);
        else if (tid < 128) cpa16(wu + 1536u + (tid - 96) * 16u, b1 + (tid - 96) * 4);
        else if (tid < 160) cpa16(wu + 2048u + (tid - 128) * 16u, b2 + (tid - 128) * 4);
        else if (tid < 192) cpa16(wu + 2560u + (tid - 160) * 16u, bc1 + (tid - 160) * 4);
        else if (tid < 196) cpa16(wu + 3072u + (tid - 192) * 16u, bf + (tid - 192) * 4);
        u32 wyu = smem_u32(wy);
#pragma unroll
        for (int i = 0; i < 2; i++)
            cpa16(wyu + (u32)(tid + i * 256) * 16u, Wc1 + 2048 + (tid + i * 256) * 4);
        cpa_commit();
        if (tid == 200) wsm[784] = __ldg(bd);
        if (tid >= 201 && tid < 204) wsm[785 + tid - 201] = __ldg(bc2 + tid - 201);
    }
    float a0x = aabb[0], a0y = aabb[1], a0z = aabb[2];
    float a1x = aabb[3], a1y = aabb[4], a1z = aabb[5];
    cpa_wait<0>();
    __syncthreads();

    // ================= per-ray-pair loop =================
#pragma unroll 1
    for (int pr = blockIdx.x; pr < N_PAIRS; pr += GRID) {
        const int ray = pr * 2 + slot;
        float ox = rays_o[ray * 3 + 0], oy = rays_o[ray * 3 + 1], oz = rays_o[ray * 3 + 2];
        float dx = rays_d[ray * 3 + 0], dy = rays_d[ray * 3 + 1], dz = rays_d[ray * 3 + 2];
        float ix = 1.f / dx, iy = 1.f / dy, iz = 1.f / dz;
        float t1x = (a0x - ox) * ix, t2x = (a1x - ox) * ix;
        float t1y = (a0y - oy) * iy, t2y = (a1y - oy) * iy;
        float t1z = (a0z - oz) * iz, t2z = (a1z - oz) * iz;
        float tn = fmaxf(fmaxf(fminf(t1x, t2x), fminf(t1y, t2y)), fminf(t1z, t2z));
        tn = fmaxf(tn, 0.f);
        float tf = fminf(fminf(fmaxf(t1x, t2x), fmaxf(t1y, t2y)), fmaxf(t1z, t2z));
        tf = fminf(tf, 10.f);
        bool active = tn < tf;
        if (!active) { tn = 0.f; tf = 1.f; }
        float dnorm = sqrtf(dx * dx + dy * dy + dz * dz);

        if (t128 == 0) {
            float inv = 1.f / dnorm;
            float x = dx * inv, y = dy * inv, z = dz * inv;
            float x2 = x * x, y2 = y * y, z2 = z * z;
            synm_s[0]  = 0.282094791773878f;
            synm_s[1]  = -0.488602511902920f * y;
            synm_s[2]  = 0.488602511902920f * z;
            synm_s[3]  = -0.488602511902920f * x;
            synm_s[4]  = 1.092548430592079f * x * y;
            synm_s[5]  = -1.092548430592079f * y * z;
            synm_s[6]  = 0.315391565252520f * (3.0f * z2 - 1.0f);
            synm_s[7]  = -1.092548430592079f * x * z;
            synm_s[8]  = 0.546274215296040f * (x2 - y2);
            synm_s[9]  = -0.590043589926644f * y * (3.0f * x2 - y2);
            synm_s[10] = 2.890611442640554f * x * y * z;
            synm_s[11] = -0.457045799464466f * y * (5.0f * z2 - 1.0f);
            synm_s[12] = 0.373176332590115f * z * (5.0f * z2 - 3.0f);
            synm_s[13] = -0.457045799464466f * x * (5.0f * z2 - 1.0f);
            synm_s[14] = 1.445305721320277f * z * (x2 - y2);
            synm_s[15] = -0.590043589926644f * x * (x2 - 3.0f * y2);
        }
        if (t128 < 64) {
            float fr = (t128 + 0.5f) * (1.f / 64.f);
            float t = tn + fr * (tf - tn);
            sts_s[t128] = t;
            float px = fmaf(dx, t, ox), py = fmaf(dy, t, oy), pz = fmaf(dz, t, oz);
            float nx = (px - a0x) / (a1x - a0x) * 2.f - 1.f;
            float ny = (py - a0y) / (a1y - a0y) * 2.f - 1.f;
            float nz = (pz - a0z) / (a1z - a0z) * 2.f - 1.f;
            sxyz_s[t128 * 3 + 0] = nx;
            sxyz_s[t128 * 3 + 1] = ny;
            sxyz_s[t128 * 3 + 2] = nz;
            bool inside = (nx >= -1.f) && (nx <= 1.f) && (ny >= -1.f) && (ny <= 1.f) &&
                          (nz >= -1.f) && (nz <= 1.f);
            sins_s[t128] = inside ? 1.f : 0.f;
        }
        __syncthreads();  // (1)

        // hcY: point-invariant ynm @ Wc1
        {
            float acc = 0.f;
#pragma unroll
            for (int j = 0; j < 16; j++)
                acc = fmaf(synm_s[j], wy[j * 128 + t128], acc);
            shcY_s[t128] = acc;
        }

        float P0x = sxyz_s[p0 * 3], P0y = sxyz_s[p0 * 3 + 1], P0z = sxyz_s[p0 * 3 + 2];
        float P1x = sxyz_s[p1 * 3], P1y = sxyz_s[p1 * 3 + 1], P1z = sxyz_s[p1 * 3 + 2];

        // ======== W2 + feat chained in two N-halves (all consumer indices static) ========
        float cf[3][4];
#pragma unroll
        for (int nt = 0; nt < 3; nt++)
#pragma unroll
            for (int i = 0; i < 4; i++) cf[nt][i] = 0.f;

#pragma unroll 1
        for (int h = 0; h < 2; h++) {
            float c[8][4];
#pragma unroll
            for (int nt = 0; nt < 8; nt++)
#pragma unroll
                for (int i = 0; i < 4; i++) c[nt][i] = 0.f;
#pragma unroll 1
            for (int ks = 0; ks < 8; ks++) {
                int j0 = ks * 16 + kq;
                float v[8];
#pragma unroll
                for (int q = 0; q < 4; q++) {
                    int j = j0 + (q & 1) + (q >> 1) * 8;
                    float w0 = wsm[j], w1 = wsm[128 + j], w2 = wsm[256 + j];
                    float bb = wsm[384 + j];
                    float h0 = fmaf(P0x, w0, bb);
                    h0 = fmaf(P0y, w1, h0);
                    h0 = fmaf(P0z, w2, h0);
                    float h1v = fmaf(P1x, w0, bb);
                    h1v = fmaf(P1y, w1, h1v);
                    h1v = fmaf(P1z, w2, h1v);
                    v[q] = fmaxf(h0, 0.f);
                    v[4 + q] = fmaxf(h1v, 0.f);
                }
                u32 ahi[4], alo[4];
                split_pack(v[0], v[1], ahi[0], alo[0]);
                split_pack(v[4], v[5], ahi[1], alo[1]);
                split_pack(v[2], v[3], ahi[2], alo[2]);
                split_pack(v[6], v[7], ahi[3], alo[3]);
                const uint4* gb = sB + (ks * 16 + h * 8) * 32 + lane;
#pragma unroll
                for (int nt = 0; nt < 8; nt++) {
                    uint4 B = gb[nt * 32];
                    mma16816(c[nt], ahi[0], ahi[1], ahi[2], ahi[3], B.x, B.y);
                    mma16816(c[nt], ahi[0], ahi[1], ahi[2], ahi[3], B.z, B.w);
                    mma16816(c[nt], alo[0], alo[1], alo[2], alo[3], B.x, B.y);
                }
            }
            // feat consumer: FULL unroll so c[] indices are compile-time
#pragma unroll
            for (int q = 0; q < 4; q++) {
                int ksf = h * 4 + q;
                int col = ksf * 16 + kq;
                float b20 = wsm[512 + col], b21 = wsm[512 + col + 1];
                float b28 = wsm[512 + col + 8], b29 = wsm[512 + col + 9];
                u32 ahi[4], alo[4];
                split_pack(fmaxf(c[2 * q][0] + b20, 0.f), fmaxf(c[2 * q][1] + b21, 0.f),
                           ahi[0], alo[0]);
                split_pack(fmaxf(c[2 * q][2] + b20, 0.f), fmaxf(c[2 * q][3] + b21, 0.f),
                           ahi[1], alo[1]);
                split_pack(fmaxf(c[2 * q + 1][0] + b28, 0.f),
                           fmaxf(c[2 * q + 1][1] + b29, 0.f), ahi[2], alo[2]);
                split_pack(fmaxf(c[2 * q + 1][2] + b28, 0.f),
                           fmaxf(c[2 * q + 1][3] + b29, 0.f), ahi[3], alo[3]);
                const uint4* gb = sB + 4096 + ksf * 3 * 32 + lane;
#pragma unroll
                for (int nt = 0; nt < 3; nt++) {
                    uint4 B = gb[nt * 32];
                    mma16816(cf[nt], ahi[0], ahi[1], ahi[2], ahi[3], B.x, B.y);
                    mma16816(cf[nt], ahi[0], ahi[1], ahi[2], ahi[3], B.z, B.w);
                    mma16816(cf[nt], alo[0], alo[1], alo[2], alo[3], B.x, B.y);
                }
            }
        }
        if ((lane & 3) == 0) {
            float bdv = wsm[784];
            ssig_s[p0] = expf(cf[2][0] + bdv) * sins_s[p0];
            ssig_s[p1] = expf(cf[2][2] + bdv) * sins_s[p1];
        }

        // feat A-fragments for c1 (K=16)
        u32 fhi[4], flo[4];
        {
            float bf0 = wsm[768 + kq], bf1 = wsm[768 + kq + 1];
            float bf8 = wsm[768 + kq + 8], bf9 = wsm[768 + kq + 9];
            split_pack(cf[0][0] + bf0, cf[0][1] + bf1, fhi[0], flo[0]);
            split_pack(cf[0][2] + bf0, cf[0][3] + bf1, fhi[1], flo[1]);
            split_pack(cf[1][0] + bf8, cf[1][1] + bf9, fhi[2], flo[2]);
            split_pack(cf[1][2] + bf8, cf[1][3] + bf9, fhi[3], flo[3]);
        }

        // ======== c1 + c2 chained in two N-halves ========
        float ccol[4] = {0.f, 0.f, 0.f, 0.f};
#pragma unroll 1
        for (int h = 0; h < 2; h++) {
            float cc[8][4];
#pragma unroll
            for (int nt = 0; nt < 8; nt++)
#pragma unroll
                for (int i = 0; i < 4; i++) cc[nt][i] = 0.f;
#pragma unroll
            for (int nt = 0; nt < 8; nt++) {
                uint4 Bf = sB[4864 + (h * 8 + nt) * 32 + lane];
                mma16816(cc[nt], fhi[0], fhi[1], fhi[2], fhi[3], Bf.x, Bf.y);
                mma16816(cc[nt], fhi[0], fhi[1], fhi[2], fhi[3], Bf.z, Bf.w);
                mma16816(cc[nt], flo[0], flo[1], flo[2], flo[3], Bf.x, Bf.y);
            }
            // c2 consumer: FULL unroll so cc[] indices are compile-time
#pragma unroll
            for (int q = 0; q < 4; q++) {
                int ksc = h * 4 + q;
                int col = ksc * 16 + kq;
                float bb0 = wsm[640 + col] + shcY_s[col];
                float bb1 = wsm[640 + col + 1] + shcY_s[col + 1];
                float bb8 = wsm[640 + col + 8] + shcY_s[col + 8];
                float bb9 = wsm[640 + col + 9] + shcY_s[col + 9];
                u32 ahi[4], alo[4];
                split_pack(fmaxf(cc[2 * q][0] + bb0, 0.f), fmaxf(cc[2 * q][1] + bb1, 0.f),
                           ahi[0], alo[0]);
                split_pack(fmaxf(cc[2 * q][2] + bb0, 0.f), fmaxf(cc[2 * q][3] + bb1, 0.f),
                           ahi[1], alo[1]);
                split_pack(fmaxf(cc[2 * q + 1][0] + bb8, 0.f),
                           fmaxf(cc[2 * q + 1][1] + bb9, 0.f), ahi[2], alo[2]);
                split_pack(fmaxf(cc[2 * q + 1][2] + bb8, 0.f),
                           fmaxf(cc[2 * q + 1][3] + bb9, 0.f), ahi[3], alo[3]);
                uint4 B = sB[5376 + ksc * 32 + lane];
                mma16816(ccol, ahi[0], ahi[1], ahi[2], ahi[3], B.x, B.y);
                mma16816(ccol, ahi[0], ahi[1], ahi[2], ahi[3], B.z, B.w);
                mma16816(ccol, alo[0], alo[1], alo[2], alo[3], B.x, B.y);
            }
        }
        {
            int cq = lane & 3;
            if (cq == 0) {
                float b0v = wsm[785], b1v = wsm[786];
                sc0_s[p0] = 1.f / (1.f + expf(-(ccol[0] + b0v)));
                sc1_s[p0] = 1.f / (1.f + expf(-(ccol[1] + b1v)));
                sc0_s[p1] = 1.f / (1.f + expf(-(ccol[2] + b0v)));
                sc1_s[p1] = 1.f / (1.f + expf(-(ccol[3] + b1v)));
            } else if (cq == 1) {
                float b2v = wsm[787];
                sc2_s[p0] = 1.f / (1.f + expf(-(ccol[0] + b2v)));
                sc2_s[p1] = 1.f / (1.f + expf(-(ccol[2] + b2v)));
            }
        }
        __syncthreads();  // (2)

        // ======== integration ========
        float tau = 0.f, tcur = 0.f, sc = 0.f;
        if (lwid < 2) {
            tcur = sts_s[t128];
            float tnext = (t128 < 63) ? sts_s[t128 + 1] : (tf + 1.0f);  // BOOSTER=1.0
            tau = ssig_s[t128] * (tnext - tcur) * dnorm;
            sc = tau;
#pragma unroll
            for (int off = 1; off < 32; off <<= 1) {
                float u = __shfl_up_sync(0xffffffffu, sc, off);
                if (lane >= off) sc += u;
            }
            if (lwid == 0 && lane == 31) sred_s[15] = sc;
        }
        __syncthreads();  // (3)
        if (lwid < 2) {
            if (lwid == 1) sc += sred_s[15];
            float excl = sc - tau;
            float wgt = expf(-excl) * (1.f - expf(-tau));
            float v0 = wgt * sc0_s[t128];
            float v1 = wgt * sc1_s[t128];
            float v2 = wgt * sc2_s[t128];
            float v3 = wgt;
            float v4 = wgt * tcur;
#pragma unroll
            for (int off = 16; off >= 1; off >>= 1) {
                v0 += __shfl_xor_sync(0xffffffffu, v0, off);
                v1 += __shfl_xor_sync(0xffffffffu, v1, off);
                v2 += __shfl_xor_sync(0xffffffffu, v2, off);
                v3 += __shfl_xor_sync(0xffffffffu, v3, off);
                v4 += __shfl_xor_sync(0xffffffffu, v4, off);
            }
            if (lane == 0) {
                sred_s[lwid * 5 + 0] = v0;
                sred_s[lwid * 5 + 1] = v1;
                sred_s[lwid * 5 + 2] = v2;
                sred_s[lwid * 5 + 3] = v3;
                sred_s[lwid * 5 + 4] = v4;
            }
        }
        __syncthreads();  // (4)
        if (t128 < 5) {
            float am = active ? 1.f : 0.f;
            out[ray * 5 + t128] = (sred_s[t128] + sred_s[5 + t128]) * am;
        }
        __syncthreads();  // (5)
    }
}

extern "C" void kernel_launch(void* const* d_in, const int* in_sizes, int n_in,
                              void* d_out, int out_size) {
    const float* rays_o = (const float*)d_in[0];
    const float* rays_d = (const float*)d_in[1];
    const float* aabb   = (const float*)d_in[2];
    const float* W1  = (const float*)d_in[3];
    const float* b1  = (const float*)d_in[4];
    const float* W2  = (const float*)d_in[5];
    const float* b2  = (const float*)d_in[6];
    const float* Wd  = (const float*)d_in[7];
    const float* bd  = (const float*)d_in[8];
    const float* Wf  = (const float*)d_in[9];
    const float* bf  = (const float*)d_in[10];
    const float* Wc1 = (const float*)d_in[11];
    const float* bc1 = (const float*)d_in[12];
    const float* Wc2 = (const float*)d_in[13];
    const float* bc2 = (const float*)d_in[14];
    float* out = (float*)d_out;

    prep_all<<<192, 32>>>(W2, Wf, Wd, Wc1, Wc2);
    size_t smem = 26848 * sizeof(float);  // 107392 B -> 2 blocks/SM
    cudaFuncSetAttribute(radiance_kernel, cudaFuncAttributeMaxDynamicSharedMemorySize,
                         (int)smem);
    radiance_kernel<<<GRID, 256, smem>>>(rays_o, rays_d, aabb, W1, b1, W2, b2, Wd, bd,
                                         Wf, bf, Wc1, bc1, Wc2, bc2, out);
}

// round 14
// speedup vs baseline: 2.9629x; 1.0684x over previous
#include <cuda_runtime.h>
#include <cuda_bf16.h>
#include <cstdint>

// ----------------------------------------------------------------------------
// RadianceRenderer R14: R13 + (a) W2 A-fragments built ONCE and cached in regs
// (AH/AL[8][4]), W2 processed in 4 N-quarters (c[4][4] live) as pure LDS+MMA
// streams, (b) __expf-based exp/sigmoid, (c) shcY race fixed with a barrier.
// Grid = 296 persistent blocks, 256 threads, 2 rays/iteration.
// ----------------------------------------------------------------------------

typedef unsigned long long ull;
typedef unsigned int u32;

#define GRID 296
#define N_PAIRS 4096   // 8192 rays / 2

// fragment-ordered B operands in GLOBAL (verified packing):
// uint4 = {hi(k0,k0+1), hi(k0+8,k0+9), lo.., lo..}; [tile][lane].
// W2 @0 (128), feat @4096 (24), c1 @4864 (32), c2 @5888 (8).
__device__ __align__(16) uint4 g_Bf[6144];

__device__ __forceinline__ void cpa16(u32 dst, const void* src) {
    asm volatile("cp.async.ca.shared.global [%0], [%1], 16;" :: "r"(dst), "l"(src));
}
__device__ __forceinline__ void cpa_commit() {
    asm volatile("cp.async.commit_group;" ::: "memory");
}
template <int N>
__device__ __forceinline__ void cpa_wait() {
    asm volatile("cp.async.wait_group %0;" :: "n"(N) : "memory");
}
__device__ __forceinline__ u32 smem_u32(const void* p) {
    return (u32)__cvta_generic_to_shared(p);
}

__device__ __forceinline__ void mma16816(float c[4], const u32 a[4], u32 b0, u32 b1) {
    asm volatile(
        "mma.sync.aligned.m16n8k16.row.col.f32.bf16.bf16.f32 "
        "{%0,%1,%2,%3}, {%4,%5,%6,%7}, {%8,%9}, {%0,%1,%2,%3};"
        : "+f"(c[0]), "+f"(c[1]), "+f"(c[2]), "+f"(c[3])
        : "r"(a[0]), "r"(a[1]), "r"(a[2]), "r"(a[3]), "r"(b0), "r"(b1));
}

// fast split: hi = {bf16(v1)|bf16(v0)}, lo = residuals, via packed cvt
__device__ __forceinline__ void split_pack(float v0, float v1, u32& hi, u32& lo) {
    u32 h;
    asm("cvt.rn.bf16x2.f32 %0, %1, %2;" : "=r"(h) : "f"(v1), "f"(v0));
    float f0 = __uint_as_float(h << 16);
    float f1 = __uint_as_float(h & 0xFFFF0000u);
    u32 l;
    asm("cvt.rn.bf16x2.f32 %0, %1, %2;" : "=r"(l) : "f"(v1 - f1), "f"(v0 - f0));
    hi = h;
    lo = l;
}

__device__ __forceinline__ float fast_sigmoid(float x) {
    return 1.f / (1.f + __expf(-x));
}

// ---------- prep: pack all B operands fragment-ordered (verified) ----------
__global__ void prep_all(const float* __restrict__ W2, const float* __restrict__ Wf,
                         const float* __restrict__ Wd, const float* __restrict__ Wc1,
                         const float* __restrict__ Wc2) {
    int b = blockIdx.x;
    int lane = threadIdx.x;
    int kq = (lane & 3) * 2, nq = lane >> 2;
    float x0, x1, x2, x3;
    uint4* dst;
    if (b < 128) {
        int ks = b >> 4, nt = b & 15;
        int k0 = ks * 16 + kq, n = nt * 8 + nq;
        x0 = W2[k0 * 128 + n];
        x1 = W2[(k0 + 1) * 128 + n];
        x2 = W2[(k0 + 8) * 128 + n];
        x3 = W2[(k0 + 9) * 128 + n];
        dst = g_Bf + b * 32 + lane;
    } else if (b < 152) {
        int idx = b - 128, ks = idx / 3, nt = idx - ks * 3;
        int k0 = ks * 16 + kq, n = nt * 8 + nq;
        auto val = [&](int k) -> float {
            if (n < 16) return Wf[k * 16 + n];
            if (n == 16) return Wd[k];
            return 0.f;
        };
        x0 = val(k0); x1 = val(k0 + 1); x2 = val(k0 + 8); x3 = val(k0 + 9);
        dst = g_Bf + 4096 + idx * 32 + lane;
    } else if (b < 184) {
        int idx = b - 152, ks = idx >> 4, nt = idx & 15;
        int k0 = ks * 16 + kq, n = nt * 8 + nq;
        x0 = Wc1[k0 * 128 + n];
        x1 = Wc1[(k0 + 1) * 128 + n];
        x2 = Wc1[(k0 + 8) * 128 + n];
        x3 = Wc1[(k0 + 9) * 128 + n];
        dst = g_Bf + 4864 + idx * 32 + lane;
    } else {
        int ks = b - 184;
        int k0 = ks * 16 + kq, n = nq;
        auto val = [&](int k) -> float { return (n < 3) ? Wc2[k * 3 + n] : 0.f; };
        x0 = val(k0); x1 = val(k0 + 1); x2 = val(k0 + 8); x3 = val(k0 + 9);
        dst = g_Bf + 5888 + ks * 32 + lane;
    }
    uint4 v;
    // use exact (non-fast) split here for clarity: same as split_pack
    split_pack(x0, x1, v.x, v.z);
    split_pack(x2, x3, v.y, v.w);
    *dst = v;
}

// smem floats: sB uint4 [0,22528)=90112B; wsm 22528..23328; wy 23328..25376;
// per-slot (x2): sxyz 25376(192ea) sts 25760(64) ssig 25888(64) sins 26016(64)
// synm 26144(16) sc0 26176(64) sc1 26304(64) sc2 26432(64) sred 26560(16)
// shcY 26592(128). total 26848 fl = 107392 B -> 2 blocks/SM.
__global__ __launch_bounds__(256, 2) void radiance_kernel(
    const float* __restrict__ rays_o, const float* __restrict__ rays_d,
    const float* __restrict__ aabb,
    const float* __restrict__ W1, const float* __restrict__ b1,
    const float* __restrict__ W2, const float* __restrict__ b2,
    const float* __restrict__ Wd, const float* __restrict__ bd,
    const float* __restrict__ Wf, const float* __restrict__ bf,
    const float* __restrict__ Wc1, const float* __restrict__ bc1,
    const float* __restrict__ Wc2, const float* __restrict__ bc2,
    float* __restrict__ out) {
    extern __shared__ float sm[];
    const uint4* sB = (const uint4*)sm;
    float* wsm = sm + 22528;
    float* wy  = sm + 23328;

    const int tid = threadIdx.x;
    const int lane = tid & 31;
    const int wid = tid >> 5;
    const int slot = tid >> 7;
    const int t128 = tid & 127;
    const int lwid = wid & 3;
    const int pb = lwid * 16;
    const int r0 = lane >> 2;
    const int p0 = pb + r0, p1 = p0 + 8;
    const int kq = (lane & 3) * 2;
    const u32 sBu = smem_u32(sm);

    float* sxyz_s = sm + 25376 + slot * 192;
    float* sts_s  = sm + 25760 + slot * 64;
    float* ssig_s = sm + 25888 + slot * 64;
    float* sins_s = sm + 26016 + slot * 64;
    float* synm_s = sm + 26144 + slot * 16;
    float* sc0_s  = sm + 26176 + slot * 64;
    float* sc1_s  = sm + 26304 + slot * 64;
    float* sc2_s  = sm + 26432 + slot * 64;
    float* sred_s = sm + 26560 + slot * 16;
    float* shcY_s = sm + 26592 + slot * 128;

    // ---- one-time staging (256 threads) ----
    {
#pragma unroll
        for (int i = 0; i < 16; i++)
            cpa16(sBu + (u32)(tid + i * 256) * 16u, g_Bf + tid + i * 256);
#pragma unroll
        for (int i = 0; i < 3; i++)
            cpa16(sBu + (u32)(4096 + tid + i * 256) * 16u, g_Bf + 4096 + tid + i * 256);
#pragma unroll
        for (int i = 0; i < 2; i++)
            cpa16(sBu + (u32)(4864 + tid + i * 256) * 16u, g_Bf + 4864 + tid + i * 256);
        cpa16(sBu + (u32)(5376 + tid) * 16u, g_Bf + 5888 + tid);
        u32 wu = smem_u32(wsm);
        if (tid < 96) cpa16(wu + tid * 16u, W1 + tid * 4);
        else if (tid < 128) cpa16(wu + 1536u + (tid - 96) * 16u, b1 + (tid - 96) * 4);
        else if (tid < 160) cpa16(wu + 2048u + (tid - 128) * 16u, b2 + (tid - 128) * 4);
        else if (tid < 192) cpa16(wu + 2560u + (tid - 160) * 16u, bc1 + (tid - 160) * 4);
        else if (tid < 196) cpa16(wu + 3072u + (tid - 192) * 16u, bf + (tid - 192) * 4);
        u32 wyu = smem_u32(wy);
#pragma unroll
        for (int i = 0; i < 2; i++)
            cpa16(wyu + (u32)(tid + i * 256) * 16u, Wc1 + 2048 + (tid + i * 256) * 4);
        cpa_commit();
        if (tid == 200) wsm[784] = __ldg(bd);
        if (tid >= 201 && tid < 204) wsm[785 + tid - 201] = __ldg(bc2 + tid - 201);
    }
    float a0x = aabb[0], a0y = aabb[1], a0z = aabb[2];
    float a1x = aabb[3], a1y = aabb[4], a1z = aabb[5];
    cpa_wait<0>();
    __syncthreads();

    // ================= per-ray-pair loop =================
#pragma unroll 1
    for (int pr = blockIdx.x; pr < N_PAIRS; pr += GRID) {
        const int ray = pr * 2 + slot;
        float ox = rays_o[ray * 3 + 0], oy = rays_o[ray * 3 + 1], oz = rays_o[ray * 3 + 2];
        float dx = rays_d[ray * 3 + 0], dy = rays_d[ray * 3 + 1], dz = rays_d[ray * 3 + 2];
        float ix = 1.f / dx, iy = 1.f / dy, iz = 1.f / dz;
        float t1x = (a0x - ox) * ix, t2x = (a1x - ox) * ix;
        float t1y = (a0y - oy) * iy, t2y = (a1y - oy) * iy;
        float t1z = (a0z - oz) * iz, t2z = (a1z - oz) * iz;
        float tn = fmaxf(fmaxf(fminf(t1x, t2x), fminf(t1y, t2y)), fminf(t1z, t2z));
        tn = fmaxf(tn, 0.f);
        float tf = fminf(fminf(fmaxf(t1x, t2x), fmaxf(t1y, t2y)), fmaxf(t1z, t2z));
        tf = fminf(tf, 10.f);
        bool active = tn < tf;
        if (!active) { tn = 0.f; tf = 1.f; }
        float dnorm = sqrtf(dx * dx + dy * dy + dz * dz);

        if (t128 == 0) {
            float inv = 1.f / dnorm;
            float x = dx * inv, y = dy * inv, z = dz * inv;
            float x2 = x * x, y2 = y * y, z2 = z * z;
            synm_s[0]  = 0.282094791773878f;
            synm_s[1]  = -0.488602511902920f * y;
            synm_s[2]  = 0.488602511902920f * z;
            synm_s[3]  = -0.488602511902920f * x;
            synm_s[4]  = 1.092548430592079f * x * y;
            synm_s[5]  = -1.092548430592079f * y * z;
            synm_s[6]  = 0.315391565252520f * (3.0f * z2 - 1.0f);
            synm_s[7]  = -1.092548430592079f * x * z;
            synm_s[8]  = 0.546274215296040f * (x2 - y2);
            synm_s[9]  = -0.590043589926644f * y * (3.0f * x2 - y2);
            synm_s[10] = 2.890611442640554f * x * y * z;
            synm_s[11] = -0.457045799464466f * y * (5.0f * z2 - 1.0f);
            synm_s[12] = 0.373176332590115f * z * (5.0f * z2 - 3.0f);
            synm_s[13] = -0.457045799464466f * x * (5.0f * z2 - 1.0f);
            synm_s[14] = 1.445305721320277f * z * (x2 - y2);
            synm_s[15] = -0.590043589926644f * x * (x2 - 3.0f * y2);
        }
        if (t128 < 64) {
            float fr = (t128 + 0.5f) * (1.f / 64.f);
            float t = tn + fr * (tf - tn);
            sts_s[t128] = t;
            float px = fmaf(dx, t, ox), py = fmaf(dy, t, oy), pz = fmaf(dz, t, oz);
            float nx = (px - a0x) / (a1x - a0x) * 2.f - 1.f;
            float ny = (py - a0y) / (a1y - a0y) * 2.f - 1.f;
            float nz = (pz - a0z) / (a1z - a0z) * 2.f - 1.f;
            sxyz_s[t128 * 3 + 0] = nx;
            sxyz_s[t128 * 3 + 1] = ny;
            sxyz_s[t128 * 3 + 2] = nz;
            bool inside = (nx >= -1.f) && (nx <= 1.f) && (ny >= -1.f) && (ny <= 1.f) &&
                          (nz >= -1.f) && (nz <= 1.f);
            sins_s[t128] = inside ? 1.f : 0.f;
        }
        __syncthreads();  // (1) setup visible

        // hcY: point-invariant ynm @ Wc1
        {
            float acc = 0.f;
#pragma unroll
            for (int j = 0; j < 16; j++)
                acc = fmaf(synm_s[j], wy[j * 128 + t128], acc);
            shcY_s[t128] = acc;
        }
        __syncthreads();  // (1b) shcY visible to all warps (race fix)

        float P0x = sxyz_s[p0 * 3], P0y = sxyz_s[p0 * 3 + 1], P0z = sxyz_s[p0 * 3 + 2];
        float P1x = sxyz_s[p1 * 3], P1y = sxyz_s[p1 * 3 + 1], P1z = sxyz_s[p1 * 3 + 2];

        // ======== build W2 A-fragments ONCE (AH/AL[8][4]) ========
        u32 AH[8][4], AL[8][4];
#pragma unroll
        for (int ks = 0; ks < 8; ks++) {
            int j0 = ks * 16 + kq;
            float v[8];
#pragma unroll
            for (int q = 0; q < 4; q++) {
                int j = j0 + (q & 1) + (q >> 1) * 8;
                float w0 = wsm[j], w1 = wsm[128 + j], w2 = wsm[256 + j];
                float bb = wsm[384 + j];
                float h0 = fmaf(P0x, w0, bb);
                h0 = fmaf(P0y, w1, h0);
                h0 = fmaf(P0z, w2, h0);
                float h1v = fmaf(P1x, w0, bb);
                h1v = fmaf(P1y, w1, h1v);
                h1v = fmaf(P1z, w2, h1v);
                v[q] = fmaxf(h0, 0.f);
                v[4 + q] = fmaxf(h1v, 0.f);
            }
            split_pack(v[0], v[1], AH[ks][0], AL[ks][0]);
            split_pack(v[4], v[5], AH[ks][1], AL[ks][1]);
            split_pack(v[2], v[3], AH[ks][2], AL[ks][2]);
            split_pack(v[6], v[7], AH[ks][3], AL[ks][3]);
        }

        // ======== W2 in 4 N-quarters (pure LDS+MMA), feat consumed per quarter ========
        float cf[3][4];
#pragma unroll
        for (int nt = 0; nt < 3; nt++)
#pragma unroll
            for (int i = 0; i < 4; i++) cf[nt][i] = 0.f;

#pragma unroll 1
        for (int qt = 0; qt < 4; qt++) {
            float c[4][4];
#pragma unroll
            for (int nt = 0; nt < 4; nt++)
#pragma unroll
                for (int i = 0; i < 4; i++) c[nt][i] = 0.f;
#pragma unroll
            for (int ks = 0; ks < 8; ks++) {
                const uint4* gb = sB + (ks * 16 + qt * 4) * 32 + lane;
#pragma unroll
                for (int nt = 0; nt < 4; nt++) {
                    uint4 B = gb[nt * 32];
                    mma16816(c[nt], AH[ks], B.x, B.y);
                    mma16816(c[nt], AH[ks], B.z, B.w);
                    mma16816(c[nt], AL[ks], B.x, B.y);
                }
            }
            // feat consumer: this quarter's h2 cols = feat k-chunks 2qt, 2qt+1
#pragma unroll
            for (int j = 0; j < 2; j++) {
                int ksf = qt * 2 + j;
                int col = ksf * 16 + kq;
                float b20 = wsm[512 + col], b21 = wsm[512 + col + 1];
                float b28 = wsm[512 + col + 8], b29 = wsm[512 + col + 9];
                u32 ahi[4], alo[4];
                split_pack(fmaxf(c[2 * j][0] + b20, 0.f), fmaxf(c[2 * j][1] + b21, 0.f),
                           ahi[0], alo[0]);
                split_pack(fmaxf(c[2 * j][2] + b20, 0.f), fmaxf(c[2 * j][3] + b21, 0.f),
                           ahi[1], alo[1]);
                split_pack(fmaxf(c[2 * j + 1][0] + b28, 0.f),
                           fmaxf(c[2 * j + 1][1] + b29, 0.f), ahi[2], alo[2]);
                split_pack(fmaxf(c[2 * j + 1][2] + b28, 0.f),
                           fmaxf(c[2 * j + 1][3] + b29, 0.f), ahi[3], alo[3]);
                const uint4* gb = sB + 4096 + ksf * 3 * 32 + lane;
#pragma unroll
                for (int nt = 0; nt < 3; nt++) {
                    uint4 B = gb[nt * 32];
                    mma16816(cf[nt], ahi, B.x, B.y);
                    mma16816(cf[nt], ahi, B.z, B.w);
                    mma16816(cf[nt], alo, B.x, B.y);
                }
            }
        }
        if ((lane & 3) == 0) {
            float bdv = wsm[784];
            ssig_s[p0] = __expf(cf[2][0] + bdv) * sins_s[p0];
            ssig_s[p1] = __expf(cf[2][2] + bdv) * sins_s[p1];
        }

        // feat A-fragments for c1 (K=16)
        u32 fhi[4], flo[4];
        {
            float bf0 = wsm[768 + kq], bf1 = wsm[768 + kq + 1];
            float bf8 = wsm[768 + kq + 8], bf9 = wsm[768 + kq + 9];
            split_pack(cf[0][0] + bf0, cf[0][1] + bf1, fhi[0], flo[0]);
            split_pack(cf[0][2] + bf0, cf[0][3] + bf1, fhi[1], flo[1]);
            split_pack(cf[1][0] + bf8, cf[1][1] + bf9, fhi[2], flo[2]);
            split_pack(cf[1][2] + bf8, cf[1][3] + bf9, fhi[3], flo[3]);
        }

        // ======== c1 + c2 chained in two N-halves ========
        float ccol[4] = {0.f, 0.f, 0.f, 0.f};
#pragma unroll 1
        for (int h = 0; h < 2; h++) {
            float cc[8][4];
#pragma unroll
            for (int nt = 0; nt < 8; nt++)
#pragma unroll
                for (int i = 0; i < 4; i++) cc[nt][i] = 0.f;
#pragma unroll
            for (int nt = 0; nt < 8; nt++) {
                uint4 Bf = sB[4864 + (h * 8 + nt) * 32 + lane];
                mma16816(cc[nt], fhi, Bf.x, Bf.y);
                mma16816(cc[nt], fhi, Bf.z, Bf.w);
                mma16816(cc[nt], flo, Bf.x, Bf.y);
            }
#pragma unroll
            for (int q = 0; q < 4; q++) {
                int ksc = h * 4 + q;
                int col = ksc * 16 + kq;
                float bb0 = wsm[640 + col] + shcY_s[col];
                float bb1 = wsm[640 + col + 1] + shcY_s[col + 1];
                float bb8 = wsm[640 + col + 8] + shcY_s[col + 8];
                float bb9 = wsm[640 + col + 9] + shcY_s[col + 9];
                u32 ahi[4], alo[4];
                split_pack(fmaxf(cc[2 * q][0] + bb0, 0.f), fmaxf(cc[2 * q][1] + bb1, 0.f),
                           ahi[0], alo[0]);
                split_pack(fmaxf(cc[2 * q][2] + bb0, 0.f), fmaxf(cc[2 * q][3] + bb1, 0.f),
                           ahi[1], alo[1]);
                split_pack(fmaxf(cc[2 * q + 1][0] + bb8, 0.f),
                           fmaxf(cc[2 * q + 1][1] + bb9, 0.f), ahi[2], alo[2]);
                split_pack(fmaxf(cc[2 * q + 1][2] + bb8, 0.f),
                           fmaxf(cc[2 * q + 1][3] + bb9, 0.f), ahi[3], alo[3]);
                uint4 B = sB[5376 + ksc * 32 + lane];
                mma16816(ccol, ahi, B.x, B.y);
                mma16816(ccol, ahi, B.z, B.w);
                mma16816(ccol, alo, B.x, B.y);
            }
        }
        {
            int cq = lane & 3;
            if (cq == 0) {
                float b0v = wsm[785], b1v = wsm[786];
                sc0_s[p0] = fast_sigmoid(ccol[0] + b0v);
                sc1_s[p0] = fast_sigmoid(ccol[1] + b1v);
                sc0_s[p1] = fast_sigmoid(ccol[2] + b0v);
                sc1_s[p1] = fast_sigmoid(ccol[3] + b1v);
            } else if (cq == 1) {
                float b2v = wsm[787];
                sc2_s[p0] = fast_sigmoid(ccol[0] + b2v);
                sc2_s[p1] = fast_sigmoid(ccol[2] + b2v);
            }
        }
        __syncthreads();  // (2) ssig, sc0-2 visible

        // ======== integration ========
        float tau = 0.f, tcur = 0.f, sc = 0.f;
        if (lwid < 2) {
            tcur = sts_s[t128];
            float tnext = (t128 < 63) ? sts_s[t128 + 1] : (tf + 1.0f);  // BOOSTER=1.0
            tau = ssig_s[t128] * (tnext - tcur) * dnorm;
            sc = tau;
#pragma unroll
            for (int off = 1; off < 32; off <<= 1) {
                float u = __shfl_up_sync(0xffffffffu, sc, off);
                if (lane >= off) sc += u;
            }
            if (lwid == 0 && lane == 31) sred_s[15] = sc;
        }
        __syncthreads();  // (3)
        if (lwid < 2) {
            if (lwid == 1) sc += sred_s[15];
            float excl = sc - tau;
            float wgt = __expf(-excl) * (1.f - __expf(-tau));
            float v0 = wgt * sc0_s[t128];
            float v1 = wgt * sc1_s[t128];
            float v2 = wgt * sc2_s[t128];
            float v3 = wgt;
            float v4 = wgt * tcur;
#pragma unroll
            for (int off = 16; off >= 1; off >>= 1) {
                v0 += __shfl_xor_sync(0xffffffffu, v0, off);
                v1 += __shfl_xor_sync(0xffffffffu, v1, off);
                v2 += __shfl_xor_sync(0xffffffffu, v2, off);
                v3 += __shfl_xor_sync(0xffffffffu, v3, off);
                v4 += __shfl_xor_sync(0xffffffffu, v4, off);
            }
            if (lane == 0) {
                sred_s[lwid * 5 + 0] = v0;
                sred_s[lwid * 5 + 1] = v1;
                sred_s[lwid * 5 + 2] = v2;
                sred_s[lwid * 5 + 3] = v3;
                sred_s[lwid * 5 + 4] = v4;
            }
        }
        __syncthreads();  // (4)
        if (t128 < 5) {
            float am = active ? 1.f : 0.f;
            out[ray * 5 + t128] = (sred_s[t128] + sred_s[5 + t128]) * am;
        }
        __syncthreads();  // (5)
    }
}

extern "C" void kernel_launch(void* const* d_in, const int* in_sizes, int n_in,
                              void* d_out, int out_size) {
    const float* rays_o = (const float*)d_in[0];
    const float* rays_d = (const float*)d_in[1];
    const float* aabb   = (const float*)d_in[2];
    const float* W1  = (const float*)d_in[3];
    const float* b1  = (const float*)d_in[4];
    const float* W2  = (const float*)d_in[5];
    const float* b2  = (const float*)d_in[6];
    const float* Wd  = (const float*)d_in[7];
    const float* bd  = (const float*)d_in[8];
    const float* Wf  = (const float*)d_in[9];
    const float* bf  = (const float*)d_in[10];
    const float* Wc1 = (const float*)d_in[11];
    const float* bc1 = (const float*)d_in[12];
    const float* Wc2 = (const float*)d_in[13];
    const float* bc2 = (const float*)d_in[14];
    float* out = (float*)d_out;

    prep_all<<<192, 32>>>(W2, Wf, Wd, Wc1, Wc2);
    size_t smem = 26848 * sizeof(float);  // 107392 B -> 2 blocks/SM
    cudaFuncSetAttribute(radiance_kernel, cudaFuncAttributeMaxDynamicSharedMemorySize,
                         (int)smem);
    radiance_kernel<<<GRID, 256, smem>>>(rays_o, rays_d, aabb, W1, b1, W2, b2, Wd, bd,
                                         Wf, bf, Wc1, bc1, Wc2, bc2, out);
}

// round 15
// speedup vs baseline: 2.9917x; 1.0097x over previous
#include <cuda_runtime.h>
#include <cuda_bf16.h>
#include <cstdint>

// ----------------------------------------------------------------------------
// RadianceRenderer R15: R14 + per-slot NAMED barriers (bar.sync slot+1, 128)
// instead of block-wide __syncthreads in the ray loop. The two ray-slots
// free-run, overlapping one slot's MMA streams with the other's scalar phases.
// Grid = 296 persistent blocks, 256 threads, 2 rays/iteration.
// ----------------------------------------------------------------------------

typedef unsigned long long ull;
typedef unsigned int u32;

#define GRID 296
#define N_PAIRS 4096   // 8192 rays / 2

// fragment-ordered B operands in GLOBAL (verified packing):
// uint4 = {hi(k0,k0+1), hi(k0+8,k0+9), lo.., lo..}; [tile][lane].
// W2 @0 (128), feat @4096 (24), c1 @4864 (32), c2 @5888 (8).
__device__ __align__(16) uint4 g_Bf[6144];

__device__ __forceinline__ void cpa16(u32 dst, const void* src) {
    asm volatile("cp.async.ca.shared.global [%0], [%1], 16;" :: "r"(dst), "l"(src));
}
__device__ __forceinline__ void cpa_commit() {
    asm volatile("cp.async.commit_group;" ::: "memory");
}
template <int N>
__device__ __forceinline__ void cpa_wait() {
    asm volatile("cp.async.wait_group %0;" :: "n"(N) : "memory");
}
__device__ __forceinline__ u32 smem_u32(const void* p) {
    return (u32)__cvta_generic_to_shared(p);
}
__device__ __forceinline__ void bar_slot(int slot) {
    asm volatile("bar.sync %0, 128;" :: "r"(slot + 1) : "memory");
}

__device__ __forceinline__ void mma16816(float c[4], const u32 a[4], u32 b0, u32 b1) {
    asm volatile(
        "mma.sync.aligned.m16n8k16.row.col.f32.bf16.bf16.f32 "
        "{%0,%1,%2,%3}, {%4,%5,%6,%7}, {%8,%9}, {%0,%1,%2,%3};"
        : "+f"(c[0]), "+f"(c[1]), "+f"(c[2]), "+f"(c[3])
        : "r"(a[0]), "r"(a[1]), "r"(a[2]), "r"(a[3]), "r"(b0), "r"(b1));
}

// fast split: hi = {bf16(v1)|bf16(v0)}, lo = residuals, via packed cvt
__device__ __forceinline__ void split_pack(float v0, float v1, u32& hi, u32& lo) {
    u32 h;
    asm("cvt.rn.bf16x2.f32 %0, %1, %2;" : "=r"(h) : "f"(v1), "f"(v0));
    float f0 = __uint_as_float(h << 16);
    float f1 = __uint_as_float(h & 0xFFFF0000u);
    u32 l;
    asm("cvt.rn.bf16x2.f32 %0, %1, %2;" : "=r"(l) : "f"(v1 - f1), "f"(v0 - f0));
    hi = h;
    lo = l;
}

__device__ __forceinline__ float fast_sigmoid(float x) {
    return 1.f / (1.f + __expf(-x));
}

// ---------- prep: pack all B operands fragment-ordered (verified) ----------
__global__ void prep_all(const float* __restrict__ W2, const float* __restrict__ Wf,
                         const float* __restrict__ Wd, const float* __restrict__ Wc1,
                         const float* __restrict__ Wc2) {
    int b = blockIdx.x;
    int lane = threadIdx.x;
    int kq = (lane & 3) * 2, nq = lane >> 2;
    float x0, x1, x2, x3;
    uint4* dst;
    if (b < 128) {
        int ks = b >> 4, nt = b & 15;
        int k0 = ks * 16 + kq, n = nt * 8 + nq;
        x0 = W2[k0 * 128 + n];
        x1 = W2[(k0 + 1) * 128 + n];
        x2 = W2[(k0 + 8) * 128 + n];
        x3 = W2[(k0 + 9) * 128 + n];
        dst = g_Bf + b * 32 + lane;
    } else if (b < 152) {
        int idx = b - 128, ks = idx / 3, nt = idx - ks * 3;
        int k0 = ks * 16 + kq, n = nt * 8 + nq;
        auto val = [&](int k) -> float {
            if (n < 16) return Wf[k * 16 + n];
            if (n == 16) return Wd[k];
            return 0.f;
        };
        x0 = val(k0); x1 = val(k0 + 1); x2 = val(k0 + 8); x3 = val(k0 + 9);
        dst = g_Bf + 4096 + idx * 32 + lane;
    } else if (b < 184) {
        int idx = b - 152, ks = idx >> 4, nt = idx & 15;
        int k0 = ks * 16 + kq, n = nt * 8 + nq;
        x0 = Wc1[k0 * 128 + n];
        x1 = Wc1[(k0 + 1) * 128 + n];
        x2 = Wc1[(k0 + 8) * 128 + n];
        x3 = Wc1[(k0 + 9) * 128 + n];
        dst = g_Bf + 4864 + idx * 32 + lane;
    } else {
        int ks = b - 184;
        int k0 = ks * 16 + kq, n = nq;
        auto val = [&](int k) -> float { return (n < 3) ? Wc2[k * 3 + n] : 0.f; };
        x0 = val(k0); x1 = val(k0 + 1); x2 = val(k0 + 8); x3 = val(k0 + 9);
        dst = g_Bf + 5888 + ks * 32 + lane;
    }
    uint4 v;
    split_pack(x0, x1, v.x, v.z);
    split_pack(x2, x3, v.y, v.w);
    *dst = v;
}

// smem floats: sB uint4 [0,22528)=90112B; wsm 22528..23328; wy 23328..25376;
// per-slot (x2): sxyz 25376(192ea) sts 25760(64) ssig 25888(64) sins 26016(64)
// synm 26144(16) sc0 26176(64) sc1 26304(64) sc2 26432(64) sred 26560(16)
// shcY 26592(128). total 26848 fl = 107392 B -> 2 blocks/SM.
__global__ __launch_bounds__(256, 2) void radiance_kernel(
    const float* __restrict__ rays_o, const float* __restrict__ rays_d,
    const float* __restrict__ aabb,
    const float* __restrict__ W1, const float* __restrict__ b1,
    const float* __restrict__ W2, const float* __restrict__ b2,
    const float* __restrict__ Wd, const float* __restrict__ bd,
    const float* __restrict__ Wf, const float* __restrict__ bf,
    const float* __restrict__ Wc1, const float* __restrict__ bc1,
    const float* __restrict__ Wc2, const float* __restrict__ bc2,
    float* __restrict__ out) {
    extern __shared__ float sm[];
    const uint4* sB = (const uint4*)sm;
    float* wsm = sm + 22528;
    float* wy  = sm + 23328;

    const int tid = threadIdx.x;
    const int lane = tid & 31;
    const int wid = tid >> 5;
    const int slot = tid >> 7;
    const int t128 = tid & 127;
    const int lwid = wid & 3;
    const int pb = lwid * 16;
    const int r0 = lane >> 2;
    const int p0 = pb + r0, p1 = p0 + 8;
    const int kq = (lane & 3) * 2;
    const u32 sBu = smem_u32(sm);

    float* sxyz_s = sm + 25376 + slot * 192;
    float* sts_s  = sm + 25760 + slot * 64;
    float* ssig_s = sm + 25888 + slot * 64;
    float* sins_s = sm + 26016 + slot * 64;
    float* synm_s = sm + 26144 + slot * 16;
    float* sc0_s  = sm + 26176 + slot * 64;
    float* sc1_s  = sm + 26304 + slot * 64;
    float* sc2_s  = sm + 26432 + slot * 64;
    float* sred_s = sm + 26560 + slot * 16;
    float* shcY_s = sm + 26592 + slot * 128;

    // ---- one-time staging (256 threads) ----
    {
#pragma unroll
        for (int i = 0; i < 16; i++)
            cpa16(sBu + (u32)(tid + i * 256) * 16u, g_Bf + tid + i * 256);
#pragma unroll
        for (int i = 0; i < 3; i++)
            cpa16(sBu + (u32)(4096 + tid + i * 256) * 16u, g_Bf + 4096 + tid + i * 256);
#pragma unroll
        for (int i = 0; i < 2; i++)
            cpa16(sBu + (u32)(4864 + tid + i * 256) * 16u, g_Bf + 4864 + tid + i * 256);
        cpa16(sBu + (u32)(5376 + tid) * 16u, g_Bf + 5888 + tid);
        u32 wu = smem_u32(wsm);
        if (tid < 96) cpa16(wu + tid * 16u, W1 + tid * 4);
        else if (tid < 128) cpa16(wu + 1536u + (tid - 96) * 16u, b1 + (tid - 96) * 4);
        else if (tid < 160) cpa16(wu + 2048u + (tid - 128) * 16u, b2 + (tid - 128) * 4);
        else if (tid < 192) cpa16(wu + 2560u + (tid - 160) * 16u, bc1 + (tid - 160) * 4);
        else if (tid < 196) cpa16(wu + 3072u + (tid - 192) * 16u, bf + (tid - 192) * 4);
        u32 wyu = smem_u32(wy);
#pragma unroll
        for (int i = 0; i < 2; i++)
            cpa16(wyu + (u32)(tid + i * 256) * 16u, Wc1 + 2048 + (tid + i * 256) * 4);
        cpa_commit();
        if (tid == 200) wsm[784] = __ldg(bd);
        if (tid >= 201 && tid < 204) wsm[785 + tid - 201] = __ldg(bc2 + tid - 201);
    }
    float a0x = aabb[0], a0y = aabb[1], a0z = aabb[2];
    float a1x = aabb[3], a1y = aabb[4], a1z = aabb[5];
    cpa_wait<0>();
    __syncthreads();  // block-wide: staging complete (only block-wide barrier)

    // ================= per-ray-pair loop (slots free-run) =================
#pragma unroll 1
    for (int pr = blockIdx.x; pr < N_PAIRS; pr += GRID) {
        const int ray = pr * 2 + slot;
        float ox = rays_o[ray * 3 + 0], oy = rays_o[ray * 3 + 1], oz = rays_o[ray * 3 + 2];
        float dx = rays_d[ray * 3 + 0], dy = rays_d[ray * 3 + 1], dz = rays_d[ray * 3 + 2];
        float ix = 1.f / dx, iy = 1.f / dy, iz = 1.f / dz;
        float t1x = (a0x - ox) * ix, t2x = (a1x - ox) * ix;
        float t1y = (a0y - oy) * iy, t2y = (a1y - oy) * iy;
        float t1z = (a0z - oz) * iz, t2z = (a1z - oz) * iz;
        float tn = fmaxf(fmaxf(fminf(t1x, t2x), fminf(t1y, t2y)), fminf(t1z, t2z));
        tn = fmaxf(tn, 0.f);
        float tf = fminf(fminf(fmaxf(t1x, t2x), fmaxf(t1y, t2y)), fmaxf(t1z, t2z));
        tf = fminf(tf, 10.f);
        bool active = tn < tf;
        if (!active) { tn = 0.f; tf = 1.f; }
        float dnorm = sqrtf(dx * dx + dy * dy + dz * dz);

        if (t128 == 0) {
            float inv = 1.f / dnorm;
            float x = dx * inv, y = dy * inv, z = dz * inv;
            float x2 = x * x, y2 = y * y, z2 = z * z;
            synm_s[0]  = 0.282094791773878f;
            synm_s[1]  = -0.488602511902920f * y;
            synm_s[2]  = 0.488602511902920f * z;
            synm_s[3]  = -0.488602511902920f * x;
            synm_s[4]  = 1.092548430592079f * x * y;
            synm_s[5]  = -1.092548430592079f * y * z;
            synm_s[6]  = 0.315391565252520f * (3.0f * z2 - 1.0f);
            synm_s[7]  = -1.092548430592079f * x * z;
            synm_s[8]  = 0.546274215296040f * (x2 - y2);
            synm_s[9]  = -0.590043589926644f * y * (3.0f * x2 - y2);
            synm_s[10] = 2.890611442640554f * x * y * z;
            synm_s[11] = -0.457045799464466f * y * (5.0f * z2 - 1.0f);
            synm_s[12] = 0.373176332590115f * z * (5.0f * z2 - 3.0f);
            synm_s[13] = -0.457045799464466f * x * (5.0f * z2 - 1.0f);
            synm_s[14] = 1.445305721320277f * z * (x2 - y2);
            synm_s[15] = -0.590043589926644f * x * (x2 - 3.0f * y2);
        }
        if (t128 < 64) {
            float fr = (t128 + 0.5f) * (1.f / 64.f);
            float t = tn + fr * (tf - tn);
            sts_s[t128] = t;
            float px = fmaf(dx, t, ox), py = fmaf(dy, t, oy), pz = fmaf(dz, t, oz);
            float nx = (px - a0x) / (a1x - a0x) * 2.f - 1.f;
            float ny = (py - a0y) / (a1y - a0y) * 2.f - 1.f;
            float nz = (pz - a0z) / (a1z - a0z) * 2.f - 1.f;
            sxyz_s[t128 * 3 + 0] = nx;
            sxyz_s[t128 * 3 + 1] = ny;
            sxyz_s[t128 * 3 + 2] = nz;
            bool inside = (nx >= -1.f) && (nx <= 1.f) && (ny >= -1.f) && (ny <= 1.f) &&
                          (nz >= -1.f) && (nz <= 1.f);
            sins_s[t128] = inside ? 1.f : 0.f;
        }
        bar_slot(slot);  // (1) setup visible (slot-local)

        // hcY: point-invariant ynm @ Wc1
        {
            float acc = 0.f;
#pragma unroll
            for (int j = 0; j < 16; j++)
                acc = fmaf(synm_s[j], wy[j * 128 + t128], acc);
            shcY_s[t128] = acc;
        }
        bar_slot(slot);  // (1b) shcY visible (slot-local)

        float P0x = sxyz_s[p0 * 3], P0y = sxyz_s[p0 * 3 + 1], P0z = sxyz_s[p0 * 3 + 2];
        float P1x = sxyz_s[p1 * 3], P1y = sxyz_s[p1 * 3 + 1], P1z = sxyz_s[p1 * 3 + 2];

        // ======== build W2 A-fragments ONCE (AH/AL[8][4]) ========
        u32 AH[8][4], AL[8][4];
#pragma unroll
        for (int ks = 0; ks < 8; ks++) {
            int j0 = ks * 16 + kq;
            float v[8];
#pragma unroll
            for (int q = 0; q < 4; q++) {
                int j = j0 + (q & 1) + (q >> 1) * 8;
                float w0 = wsm[j], w1 = wsm[128 + j], w2 = wsm[256 + j];
                float bb = wsm[384 + j];
                float h0 = fmaf(P0x, w0, bb);
                h0 = fmaf(P0y, w1, h0);
                h0 = fmaf(P0z, w2, h0);
                float h1v = fmaf(P1x, w0, bb);
                h1v = fmaf(P1y, w1, h1v);
                h1v = fmaf(P1z, w2, h1v);
                v[q] = fmaxf(h0, 0.f);
                v[4 + q] = fmaxf(h1v, 0.f);
            }
            split_pack(v[0], v[1], AH[ks][0], AL[ks][0]);
            split_pack(v[4], v[5], AH[ks][1], AL[ks][1]);
            split_pack(v[2], v[3], AH[ks][2], AL[ks][2]);
            split_pack(v[6], v[7], AH[ks][3], AL[ks][3]);
        }

        // ======== W2 in 4 N-quarters, feat consumed per quarter ========
        float cf[3][4];
#pragma unroll
        for (int nt = 0; nt < 3; nt++)
#pragma unroll
            for (int i = 0; i < 4; i++) cf[nt][i] = 0.f;

#pragma unroll 1
        for (int qt = 0; qt < 4; qt++) {
            float c[4][4];
#pragma unroll
            for (int nt = 0; nt < 4; nt++)
#pragma unroll
                for (int i = 0; i < 4; i++) c[nt][i] = 0.f;
#pragma unroll
            for (int ks = 0; ks < 8; ks++) {
                const uint4* gb = sB + (ks * 16 + qt * 4) * 32 + lane;
#pragma unroll
                for (int nt = 0; nt < 4; nt++) {
                    uint4 B = gb[nt * 32];
                    mma16816(c[nt], AH[ks], B.x, B.y);
                    mma16816(c[nt], AH[ks], B.z, B.w);
                    mma16816(c[nt], AL[ks], B.x, B.y);
                }
            }
#pragma unroll
            for (int j = 0; j < 2; j++) {
                int ksf = qt * 2 + j;
                int col = ksf * 16 + kq;
                float b20 = wsm[512 + col], b21 = wsm[512 + col + 1];
                float b28 = wsm[512 + col + 8], b29 = wsm[512 + col + 9];
                u32 ahi[4], alo[4];
                split_pack(fmaxf(c[2 * j][0] + b20, 0.f), fmaxf(c[2 * j][1] + b21, 0.f),
                           ahi[0], alo[0]);
                split_pack(fmaxf(c[2 * j][2] + b20, 0.f), fmaxf(c[2 * j][3] + b21, 0.f),
                           ahi[1], alo[1]);
                split_pack(fmaxf(c[2 * j + 1][0] + b28, 0.f),
                           fmaxf(c[2 * j + 1][1] + b29, 0.f), ahi[2], alo[2]);
                split_pack(fmaxf(c[2 * j + 1][2] + b28, 0.f),
                           fmaxf(c[2 * j + 1][3] + b29, 0.f), ahi[3], alo[3]);
                const uint4* gb = sB + 4096 + ksf * 3 * 32 + lane;
#pragma unroll
                for (int nt = 0; nt < 3; nt++) {
                    uint4 B = gb[nt * 32];
                    mma16816(cf[nt], ahi, B.x, B.y);
                    mma16816(cf[nt], ahi, B.z, B.w);
                    mma16816(cf[nt], alo, B.x, B.y);
                }
            }
        }
        if ((lane & 3) == 0) {
            float bdv = wsm[784];
            ssig_s[p0] = __expf(cf[2][0] + bdv) * sins_s[p0];
            ssig_s[p1] = __expf(cf[2][2] + bdv) * sins_s[p1];
        }

        // feat A-fragments for c1 (K=16)
        u32 fhi[4], flo[4];
        {
            float bf0 = wsm[768 + kq], bf1 = wsm[768 + kq + 1];
            float bf8 = wsm[768 + kq + 8], bf9 = wsm[768 + kq + 9];
            split_pack(cf[0][0] + bf0, cf[0][1] + bf1, fhi[0], flo[0]);
            split_pack(cf[0][2] + bf0, cf[0][3] + bf1, fhi[1], flo[1]);
            split_pack(cf[1][0] + bf8, cf[1][1] + bf9, fhi[2], flo[2]);
            split_pack(cf[1][2] + bf8, cf[1][3] + bf9, fhi[3], flo[3]);
        }

        // ======== c1 + c2 chained in two N-halves ========
        float ccol[4] = {0.f, 0.f, 0.f, 0.f};
#pragma unroll 1
        for (int h = 0; h < 2; h++) {
            float cc[8][4];
#pragma unroll
            for (int nt = 0; nt < 8; nt++)
#pragma unroll
                for (int i = 0; i < 4; i++) cc[nt][i] = 0.f;
#pragma unroll
            for (int nt = 0; nt < 8; nt++) {
                uint4 Bf = sB[4864 + (h * 8 + nt) * 32 + lane];
                mma16816(cc[nt], fhi, Bf.x, Bf.y);
                mma16816(cc[nt], fhi, Bf.z, Bf.w);
                mma16816(cc[nt], flo, Bf.x, Bf.y);
            }
#pragma unroll
            for (int q = 0; q < 4; q++) {
                int ksc = h * 4 + q;
                int col = ksc * 16 + kq;
                float bb0 = wsm[640 + col] + shcY_s[col];
                float bb1 = wsm[640 + col + 1] + shcY_s[col + 1];
                float bb8 = wsm[640 + col + 8] + shcY_s[col + 8];
                float bb9 = wsm[640 + col + 9] + shcY_s[col + 9];
                u32 ahi[4], alo[4];
                split_pack(fmaxf(cc[2 * q][0] + bb0, 0.f), fmaxf(cc[2 * q][1] + bb1, 0.f),
                           ahi[0], alo[0]);
                split_pack(fmaxf(cc[2 * q][2] + bb0, 0.f), fmaxf(cc[2 * q][3] + bb1, 0.f),
                           ahi[1], alo[1]);
                split_pack(fmaxf(cc[2 * q + 1][0] + bb8, 0.f),
                           fmaxf(cc[2 * q + 1][1] + bb9, 0.f), ahi[2], alo[2]);
                split_pack(fmaxf(cc[2 * q + 1][2] + bb8, 0.f),
                           fmaxf(cc[2 * q + 1][3] + bb9, 0.f), ahi[3], alo[3]);
                uint4 B = sB[5376 + ksc * 32 + lane];
                mma16816(ccol, ahi, B.x, B.y);
                mma16816(ccol, ahi, B.z, B.w);
                mma16816(ccol, alo, B.x, B.y);
            }
        }
        {
            int cq = lane & 3;
            if (cq == 0) {
                float b0v = wsm[785], b1v = wsm[786];
                sc0_s[p0] = fast_sigmoid(ccol[0] + b0v);
                sc1_s[p0] = fast_sigmoid(ccol[1] + b1v);
                sc0_s[p1] = fast_sigmoid(ccol[2] + b0v);
                sc1_s[p1] = fast_sigmoid(ccol[3] + b1v);
            } else if (cq == 1) {
                float b2v = wsm[787];
                sc2_s[p0] = fast_sigmoid(ccol[0] + b2v);
                sc2_s[p1] = fast_sigmoid(ccol[2] + b2v);
            }
        }
        bar_slot(slot);  // (2) ssig, sc0-2 visible (slot-local)

        // ======== integration ========
        float tau = 0.f, tcur = 0.f, sc = 0.f;
        if (lwid < 2) {
            tcur = sts_s[t128];
            float tnext = (t128 < 63) ? sts_s[t128 + 1] : (tf + 1.0f);  // BOOSTER=1.0
            tau = ssig_s[t128] * (tnext - tcur) * dnorm;
            sc = tau;
#pragma unroll
            for (int off = 1; off < 32; off <<= 1) {
                float u = __shfl_up_sync(0xffffffffu, sc, off);
                if (lane >= off) sc += u;
            }
            if (lwid == 0 && lane == 31) sred_s[15] = sc;
        }
        bar_slot(slot);  // (3)
        if (lwid < 2) {
            if (lwid == 1) sc += sred_s[15];
            float excl = sc - tau;
            float wgt = __expf(-excl) * (1.f - __expf(-tau));
            float v0 = wgt * sc0_s[t128];
            float v1 = wgt * sc1_s[t128];
            float v2 = wgt * sc2_s[t128];
            float v3 = wgt;
            float v4 = wgt * tcur;
#pragma unroll
            for (int off = 16; off >= 1; off >>= 1) {
                v0 += __shfl_xor_sync(0xffffffffu, v0, off);
                v1 += __shfl_xor_sync(0xffffffffu, v1, off);
                v2 += __shfl_xor_sync(0xffffffffu, v2, off);
                v3 += __shfl_xor_sync(0xffffffffu, v3, off);
                v4 += __shfl_xor_sync(0xffffffffu, v4, off);
            }
            if (lane == 0) {
                sred_s[lwid * 5 + 0] = v0;
                sred_s[lwid * 5 + 1] = v1;
                sred_s[lwid * 5 + 2] = v2;
                sred_s[lwid * 5 + 3] = v3;
                sred_s[lwid * 5 + 4] = v4;
            }
        }
        bar_slot(slot);  // (4)
        if (t128 < 5) {
            float am = active ? 1.f : 0.f;
            out[ray * 5 + t128] = (sred_s[t128] + sred_s[5 + t128]) * am;
        }
        bar_slot(slot);  // (5) protect reused buffers (slot-local)
    }
}

extern "C" void kernel_launch(void* const* d_in, const int* in_sizes, int n_in,
                              void* d_out, int out_size) {
    const float* rays_o = (const float*)d_in[0];
    const float* rays_d = (const float*)d_in[1];
    const float* aabb   = (const float*)d_in[2];
    const float* W1  = (const float*)d_in[3];
    const float* b1  = (const float*)d_in[4];
    const float* W2  = (const float*)d_in[5];
    const float* b2  = (const float*)d_in[6];
    const float* Wd  = (const float*)d_in[7];
    const float* bd  = (const float*)d_in[8];
    const float* Wf  = (const float*)d_in[9];
    const float* bf  = (const float*)d_in[10];
    const float* Wc1 = (const float*)d_in[11];
    const float* bc1 = (const float*)d_in[12];
    const float* Wc2 = (const float*)d_in[13];
    const float* bc2 = (const float*)d_in[14];
    float* out = (float*)d_out;

    prep_all<<<192, 32>>>(W2, Wf, Wd, Wc1, Wc2);
    size_t smem = 26848 * sizeof(float);  // 107392 B -> 2 blocks/SM
    cudaFuncSetAttribute(radiance_kernel, cudaFuncAttributeMaxDynamicSharedMemorySize,
                         (int)smem);
    radiance_kernel<<<GRID, 256, smem>>>(rays_o, rays_d, aabb, W1, b1, W2, b2, Wd, bd,
                                         Wf, bf, Wc1, bc1, Wc2, bc2, out);
}

// round 16
// speedup vs baseline: 3.0455x; 1.0180x over previous
#include <cuda_runtime.h>
#include <cuda_bf16.h>
#include <cstdint>

// ----------------------------------------------------------------------------
// RadianceRenderer R16: R15 + (a) bc1 folded into the per-ray hcY vector,
// (b) qt/h phase loops fully unrolled (immediate smem offsets; consumer packing
// overlaps next quarter's MMA stream). Accumulator indices all compile-time.
// Grid = 296 persistent blocks, 256 threads, 2 rays/iteration.
// ----------------------------------------------------------------------------

typedef unsigned long long ull;
typedef unsigned int u32;

#define GRID 296
#define N_PAIRS 4096   // 8192 rays / 2

// fragment-ordered B operands in GLOBAL (verified packing):
// uint4 = {hi(k0,k0+1), hi(k0+8,k0+9), lo.., lo..}; [tile][lane].
// W2 @0 (128), feat @4096 (24), c1 @4864 (32), c2 @5888 (8).
__device__ __align__(16) uint4 g_Bf[6144];

__device__ __forceinline__ void cpa16(u32 dst, const void* src) {
    asm volatile("cp.async.ca.shared.global [%0], [%1], 16;" :: "r"(dst), "l"(src));
}
__device__ __forceinline__ void cpa_commit() {
    asm volatile("cp.async.commit_group;" ::: "memory");
}
template <int N>
__device__ __forceinline__ void cpa_wait() {
    asm volatile("cp.async.wait_group %0;" :: "n"(N) : "memory");
}
__device__ __forceinline__ u32 smem_u32(const void* p) {
    return (u32)__cvta_generic_to_shared(p);
}
__device__ __forceinline__ void bar_slot(int slot) {
    asm volatile("bar.sync %0, 128;" :: "r"(slot + 1) : "memory");
}

__device__ __forceinline__ void mma16816(float c[4], const u32 a[4], u32 b0, u32 b1) {
    asm volatile(
        "mma.sync.aligned.m16n8k16.row.col.f32.bf16.bf16.f32 "
        "{%0,%1,%2,%3}, {%4,%5,%6,%7}, {%8,%9}, {%0,%1,%2,%3};"
        : "+f"(c[0]), "+f"(c[1]), "+f"(c[2]), "+f"(c[3])
        : "r"(a[0]), "r"(a[1]), "r"(a[2]), "r"(a[3]), "r"(b0), "r"(b1));
}

// fast split: hi = {bf16(v1)|bf16(v0)}, lo = residuals, via packed cvt
__device__ __forceinline__ void split_pack(float v0, float v1, u32& hi, u32& lo) {
    u32 h;
    asm("cvt.rn.bf16x2.f32 %0, %1, %2;" : "=r"(h) : "f"(v1), "f"(v0));
    float f0 = __uint_as_float(h << 16);
    float f1 = __uint_as_float(h & 0xFFFF0000u);
    u32 l;
    asm("cvt.rn.bf16x2.f32 %0, %1, %2;" : "=r"(l) : "f"(v1 - f1), "f"(v0 - f0));
    hi = h;
    lo = l;
}

__device__ __forceinline__ float fast_sigmoid(float x) {
    return 1.f / (1.f + __expf(-x));
}

// ---------- prep: pack all B operands fragment-ordered (verified) ----------
__global__ void prep_all(const float* __restrict__ W2, const float* __restrict__ Wf,
                         const float* __restrict__ Wd, const float* __restrict__ Wc1,
                         const float* __restrict__ Wc2) {
    int b = blockIdx.x;
    int lane = threadIdx.x;
    int kq = (lane & 3) * 2, nq = lane >> 2;
    float x0, x1, x2, x3;
    uint4* dst;
    if (b < 128) {
        int ks = b >> 4, nt = b & 15;
        int k0 = ks * 16 + kq, n = nt * 8 + nq;
        x0 = W2[k0 * 128 + n];
        x1 = W2[(k0 + 1) * 128 + n];
        x2 = W2[(k0 + 8) * 128 + n];
        x3 = W2[(k0 + 9) * 128 + n];
        dst = g_Bf + b * 32 + lane;
    } else if (b < 152) {
        int idx = b - 128, ks = idx / 3, nt = idx - ks * 3;
        int k0 = ks * 16 + kq, n = nt * 8 + nq;
        auto val = [&](int k) -> float {
            if (n < 16) return Wf[k * 16 + n];
            if (n == 16) return Wd[k];
            return 0.f;
        };
        x0 = val(k0); x1 = val(k0 + 1); x2 = val(k0 + 8); x3 = val(k0 + 9);
        dst = g_Bf + 4096 + idx * 32 + lane;
    } else if (b < 184) {
        int idx = b - 152, ks = idx >> 4, nt = idx & 15;
        int k0 = ks * 16 + kq, n = nt * 8 + nq;
        x0 = Wc1[k0 * 128 + n];
        x1 = Wc1[(k0 + 1) * 128 + n];
        x2 = Wc1[(k0 + 8) * 128 + n];
        x3 = Wc1[(k0 + 9) * 128 + n];
        dst = g_Bf + 4864 + idx * 32 + lane;
    } else {
        int ks = b - 184;
        int k0 = ks * 16 + kq, n = nq;
        auto val = [&](int k) -> float { return (n < 3) ? Wc2[k * 3 + n] : 0.f; };
        x0 = val(k0); x1 = val(k0 + 1); x2 = val(k0 + 8); x3 = val(k0 + 9);
        dst = g_Bf + 5888 + ks * 32 + lane;
    }
    uint4 v;
    split_pack(x0, x1, v.x, v.z);
    split_pack(x2, x3, v.y, v.w);
    *dst = v;
}

// smem floats: sB uint4 [0,22528)=90112B; wsm 22528..23328; wy 23328..25376;
// per-slot (x2): sxyz 25376(192ea) sts 25760(64) ssig 25888(64) sins 26016(64)
// synm 26144(16) sc0 26176(64) sc1 26304(64) sc2 26432(64) sred 26560(16)
// shcY 26592(128). total 26848 fl = 107392 B -> 2 blocks/SM.
__global__ __launch_bounds__(256, 2) void radiance_kernel(
    const float* __restrict__ rays_o, const float* __restrict__ rays_d,
    const float* __restrict__ aabb,
    const float* __restrict__ W1, const float* __restrict__ b1,
    const float* __restrict__ W2, const float* __restrict__ b2,
    const float* __restrict__ Wd, const float* __restrict__ bd,
    const float* __restrict__ Wf, const float* __restrict__ bf,
    const float* __restrict__ Wc1, const float* __restrict__ bc1,
    const float* __restrict__ Wc2, const float* __restrict__ bc2,
    float* __restrict__ out) {
    extern __shared__ float sm[];
    const uint4* sB = (const uint4*)sm;
    float* wsm = sm + 22528;
    float* wy  = sm + 23328;

    const int tid = threadIdx.x;
    const int lane = tid & 31;
    const int wid = tid >> 5;
    const int slot = tid >> 7;
    const int t128 = tid & 127;
    const int lwid = wid & 3;
    const int pb = lwid * 16;
    const int r0 = lane >> 2;
    const int p0 = pb + r0, p1 = p0 + 8;
    const int kq = (lane & 3) * 2;
    const u32 sBu = smem_u32(sm);

    float* sxyz_s = sm + 25376 + slot * 192;
    float* sts_s  = sm + 25760 + slot * 64;
    float* ssig_s = sm + 25888 + slot * 64;
    float* sins_s = sm + 26016 + slot * 64;
    float* synm_s = sm + 26144 + slot * 16;
    float* sc0_s  = sm + 26176 + slot * 64;
    float* sc1_s  = sm + 26304 + slot * 64;
    float* sc2_s  = sm + 26432 + slot * 64;
    float* sred_s = sm + 26560 + slot * 16;
    float* shcY_s = sm + 26592 + slot * 128;

    // ---- one-time staging (256 threads) ----
    {
#pragma unroll
        for (int i = 0; i < 16; i++)
            cpa16(sBu + (u32)(tid + i * 256) * 16u, g_Bf + tid + i * 256);
#pragma unroll
        for (int i = 0; i < 3; i++)
            cpa16(sBu + (u32)(4096 + tid + i * 256) * 16u, g_Bf + 4096 + tid + i * 256);
#pragma unroll
        for (int i = 0; i < 2; i++)
            cpa16(sBu + (u32)(4864 + tid + i * 256) * 16u, g_Bf + 4864 + tid + i * 256);
        cpa16(sBu + (u32)(5376 + tid) * 16u, g_Bf + 5888 + tid);
        u32 wu = smem_u32(wsm);
        if (tid < 96) cpa16(wu + tid * 16u, W1 + tid * 4);
        else if (tid < 128) cpa16(wu + 1536u + (tid - 96) * 16u, b1 + (tid - 96) * 4);
        else if (tid < 160) cpa16(wu + 2048u + (tid - 128) * 16u, b2 + (tid - 128) * 4);
        else if (tid < 192) cpa16(wu + 2560u + (tid - 160) * 16u, bc1 + (tid - 160) * 4);
        else if (tid < 196) cpa16(wu + 3072u + (tid - 192) * 16u, bf + (tid - 192) * 4);
        u32 wyu = smem_u32(wy);
#pragma unroll
        for (int i = 0; i < 2; i++)
            cpa16(wyu + (u32)(tid + i * 256) * 16u, Wc1 + 2048 + (tid + i * 256) * 4);
        cpa_commit();
        if (tid == 200) wsm[784] = __ldg(bd);
        if (tid >= 201 && tid < 204) wsm[785 + tid - 201] = __ldg(bc2 + tid - 201);
    }
    float a0x = aabb[0], a0y = aabb[1], a0z = aabb[2];
    float a1x = aabb[3], a1y = aabb[4], a1z = aabb[5];
    cpa_wait<0>();
    __syncthreads();  // block-wide: staging complete

    // ================= per-ray-pair loop (slots free-run) =================
#pragma unroll 1
    for (int pr = blockIdx.x; pr < N_PAIRS; pr += GRID) {
        const int ray = pr * 2 + slot;
        float ox = rays_o[ray * 3 + 0], oy = rays_o[ray * 3 + 1], oz = rays_o[ray * 3 + 2];
        float dx = rays_d[ray * 3 + 0], dy = rays_d[ray * 3 + 1], dz = rays_d[ray * 3 + 2];
        float ix = 1.f / dx, iy = 1.f / dy, iz = 1.f / dz;
        float t1x = (a0x - ox) * ix, t2x = (a1x - ox) * ix;
        float t1y = (a0y - oy) * iy, t2y = (a1y - oy) * iy;
        float t1z = (a0z - oz) * iz, t2z = (a1z - oz) * iz;
        float tn = fmaxf(fmaxf(fminf(t1x, t2x), fminf(t1y, t2y)), fminf(t1z, t2z));
        tn = fmaxf(tn, 0.f);
        float tf = fminf(fminf(fmaxf(t1x, t2x), fmaxf(t1y, t2y)), fmaxf(t1z, t2z));
        tf = fminf(tf, 10.f);
        bool active = tn < tf;
        if (!active) { tn = 0.f; tf = 1.f; }
        float dnorm = sqrtf(dx * dx + dy * dy + dz * dz);

        if (t128 == 0) {
            float inv = 1.f / dnorm;
            float x = dx * inv, y = dy * inv, z = dz * inv;
            float x2 = x * x, y2 = y * y, z2 = z * z;
            synm_s[0]  = 0.282094791773878f;
            synm_s[1]  = -0.488602511902920f * y;
            synm_s[2]  = 0.488602511902920f * z;
            synm_s[3]  = -0.488602511902920f * x;
            synm_s[4]  = 1.092548430592079f * x * y;
            synm_s[5]  = -1.092548430592079f * y * z;
            synm_s[6]  = 0.315391565252520f * (3.0f * z2 - 1.0f);
            synm_s[7]  = -1.092548430592079f * x * z;
            synm_s[8]  = 0.546274215296040f * (x2 - y2);
            synm_s[9]  = -0.590043589926644f * y * (3.0f * x2 - y2);
            synm_s[10] = 2.890611442640554f * x * y * z;
            synm_s[11] = -0.457045799464466f * y * (5.0f * z2 - 1.0f);
            synm_s[12] = 0.373176332590115f * z * (5.0f * z2 - 3.0f);
            synm_s[13] = -0.457045799464466f * x * (5.0f * z2 - 1.0f);
            synm_s[14] = 1.445305721320277f * z * (x2 - y2);
            synm_s[15] = -0.590043589926644f * x * (x2 - 3.0f * y2);
        }
        if (t128 < 64) {
            float fr = (t128 + 0.5f) * (1.f / 64.f);
            float t = tn + fr * (tf - tn);
            sts_s[t128] = t;
            float px = fmaf(dx, t, ox), py = fmaf(dy, t, oy), pz = fmaf(dz, t, oz);
            float nx = (px - a0x) / (a1x - a0x) * 2.f - 1.f;
            float ny = (py - a0y) / (a1y - a0y) * 2.f - 1.f;
            float nz = (pz - a0z) / (a1z - a0z) * 2.f - 1.f;
            sxyz_s[t128 * 3 + 0] = nx;
            sxyz_s[t128 * 3 + 1] = ny;
            sxyz_s[t128 * 3 + 2] = nz;
            bool inside = (nx >= -1.f) && (nx <= 1.f) && (ny >= -1.f) && (ny <= 1.f) &&
                          (nz >= -1.f) && (nz <= 1.f);
            sins_s[t128] = inside ? 1.f : 0.f;
        }
        bar_slot(slot);  // (1) setup visible

        // hcY: point-invariant (ynm @ Wc1) + bc1 folded in
        {
            float acc = wsm[640 + t128];  // bc1
#pragma unroll
            for (int j = 0; j < 16; j++)
                acc = fmaf(synm_s[j], wy[j * 128 + t128], acc);
            shcY_s[t128] = acc;
        }
        bar_slot(slot);  // (1b) shcY visible

        float P0x = sxyz_s[p0 * 3], P0y = sxyz_s[p0 * 3 + 1], P0z = sxyz_s[p0 * 3 + 2];
        float P1x = sxyz_s[p1 * 3], P1y = sxyz_s[p1 * 3 + 1], P1z = sxyz_s[p1 * 3 + 2];

        // ======== build W2 A-fragments ONCE (AH/AL[8][4]) ========
        u32 AH[8][4], AL[8][4];
#pragma unroll
        for (int ks = 0; ks < 8; ks++) {
            int j0 = ks * 16 + kq;
            float v[8];
#pragma unroll
            for (int q = 0; q < 4; q++) {
                int j = j0 + (q & 1) + (q >> 1) * 8;
                float w0 = wsm[j], w1 = wsm[128 + j], w2 = wsm[256 + j];
                float bb = wsm[384 + j];
                float h0 = fmaf(P0x, w0, bb);
                h0 = fmaf(P0y, w1, h0);
                h0 = fmaf(P0z, w2, h0);
                float h1v = fmaf(P1x, w0, bb);
                h1v = fmaf(P1y, w1, h1v);
                h1v = fmaf(P1z, w2, h1v);
                v[q] = fmaxf(h0, 0.f);
                v[4 + q] = fmaxf(h1v, 0.f);
            }
            split_pack(v[0], v[1], AH[ks][0], AL[ks][0]);
            split_pack(v[4], v[5], AH[ks][1], AL[ks][1]);
            split_pack(v[2], v[3], AH[ks][2], AL[ks][2]);
            split_pack(v[6], v[7], AH[ks][3], AL[ks][3]);
        }

        // ======== W2 in 4 N-quarters (FULLY UNROLLED), feat per quarter ========
        float cf[3][4];
#pragma unroll
        for (int nt = 0; nt < 3; nt++)
#pragma unroll
            for (int i = 0; i < 4; i++) cf[nt][i] = 0.f;

#pragma unroll
        for (int qt = 0; qt < 4; qt++) {
            float c[4][4];
#pragma unroll
            for (int nt = 0; nt < 4; nt++)
#pragma unroll
                for (int i = 0; i < 4; i++) c[nt][i] = 0.f;
#pragma unroll
            for (int ks = 0; ks < 8; ks++) {
                const uint4* gb = sB + (ks * 16 + qt * 4) * 32 + lane;
#pragma unroll
                for (int nt = 0; nt < 4; nt++) {
                    uint4 B = gb[nt * 32];
                    mma16816(c[nt], AH[ks], B.x, B.y);
                    mma16816(c[nt], AH[ks], B.z, B.w);
                    mma16816(c[nt], AL[ks], B.x, B.y);
                }
            }
#pragma unroll
            for (int j = 0; j < 2; j++) {
                int ksf = qt * 2 + j;
                int col = ksf * 16 + kq;
                float b20 = wsm[512 + col], b21 = wsm[512 + col + 1];
                float b28 = wsm[512 + col + 8], b29 = wsm[512 + col + 9];
                u32 ahi[4], alo[4];
                split_pack(fmaxf(c[2 * j][0] + b20, 0.f), fmaxf(c[2 * j][1] + b21, 0.f),
                           ahi[0], alo[0]);
                split_pack(fmaxf(c[2 * j][2] + b20, 0.f), fmaxf(c[2 * j][3] + b21, 0.f),
                           ahi[1], alo[1]);
                split_pack(fmaxf(c[2 * j + 1][0] + b28, 0.f),
                           fmaxf(c[2 * j + 1][1] + b29, 0.f), ahi[2], alo[2]);
                split_pack(fmaxf(c[2 * j + 1][2] + b28, 0.f),
                           fmaxf(c[2 * j + 1][3] + b29, 0.f), ahi[3], alo[3]);
                const uint4* gb = sB + 4096 + ksf * 3 * 32 + lane;
#pragma unroll
                for (int nt = 0; nt < 3; nt++) {
                    uint4 B = gb[nt * 32];
                    mma16816(cf[nt], ahi, B.x, B.y);
                    mma16816(cf[nt], ahi, B.z, B.w);
                    mma16816(cf[nt], alo, B.x, B.y);
                }
            }
        }
        if ((lane & 3) == 0) {
            float bdv = wsm[784];
            ssig_s[p0] = __expf(cf[2][0] + bdv) * sins_s[p0];
            ssig_s[p1] = __expf(cf[2][2] + bdv) * sins_s[p1];
        }

        // feat A-fragments for c1 (K=16)
        u32 fhi[4], flo[4];
        {
            float bf0 = wsm[768 + kq], bf1 = wsm[768 + kq + 1];
            float bf8 = wsm[768 + kq + 8], bf9 = wsm[768 + kq + 9];
            split_pack(cf[0][0] + bf0, cf[0][1] + bf1, fhi[0], flo[0]);
            split_pack(cf[0][2] + bf0, cf[0][3] + bf1, fhi[1], flo[1]);
            split_pack(cf[1][0] + bf8, cf[1][1] + bf9, fhi[2], flo[2]);
            split_pack(cf[1][2] + bf8, cf[1][3] + bf9, fhi[3], flo[3]);
        }

        // ======== c1 + c2 chained in two N-halves (FULLY UNROLLED) ========
        float ccol[4] = {0.f, 0.f, 0.f, 0.f};
#pragma unroll
        for (int h = 0; h < 2; h++) {
            float cc[8][4];
#pragma unroll
            for (int nt = 0; nt < 8; nt++)
#pragma unroll
                for (int i = 0; i < 4; i++) cc[nt][i] = 0.f;
#pragma unroll
            for (int nt = 0; nt < 8; nt++) {
                uint4 Bf = sB[4864 + (h * 8 + nt) * 32 + lane];
                mma16816(cc[nt], fhi, Bf.x, Bf.y);
                mma16816(cc[nt], fhi, Bf.z, Bf.w);
                mma16816(cc[nt], flo, Bf.x, Bf.y);
            }
#pragma unroll
            for (int q = 0; q < 4; q++) {
                int ksc = h * 4 + q;
                int col = ksc * 16 + kq;
                float bb0 = shcY_s[col];       // bc1 already folded in
                float bb1 = shcY_s[col + 1];
                float bb8 = shcY_s[col + 8];
                float bb9 = shcY_s[col + 9];
                u32 ahi[4], alo[4];
                split_pack(fmaxf(cc[2 * q][0] + bb0, 0.f), fmaxf(cc[2 * q][1] + bb1, 0.f),
                           ahi[0], alo[0]);
                split_pack(fmaxf(cc[2 * q][2] + bb0, 0.f), fmaxf(cc[2 * q][3] + bb1, 0.f),
                           ahi[1], alo[1]);
                split_pack(fmaxf(cc[2 * q + 1][0] + bb8, 0.f),
                           fmaxf(cc[2 * q + 1][1] + bb9, 0.f), ahi[2], alo[2]);
                split_pack(fmaxf(cc[2 * q + 1][2] + bb8, 0.f),
                           fmaxf(cc[2 * q + 1][3] + bb9, 0.f), ahi[3], alo[3]);
                uint4 B = sB[5376 + ksc * 32 + lane];
                mma16816(ccol, ahi, B.x, B.y);
                mma16816(ccol, ahi, B.z, B.w);
                mma16816(ccol, alo, B.x, B.y);
            }
        }
        {
            int cq = lane & 3;
            if (cq == 0) {
                float b0v = wsm[785], b1v = wsm[786];
                sc0_s[p0] = fast_sigmoid(ccol[0] + b0v);
                sc1_s[p0] = fast_sigmoid(ccol[1] + b1v);
                sc0_s[p1] = fast_sigmoid(ccol[2] + b0v);
                sc1_s[p1] = fast_sigmoid(ccol[3] + b1v);
            } else if (cq == 1) {
                float b2v = wsm[787];
                sc2_s[p0] = fast_sigmoid(ccol[0] + b2v);
                sc2_s[p1] = fast_sigmoid(ccol[2] + b2v);
            }
        }
        bar_slot(slot);  // (2) ssig, sc0-2 visible

        // ======== integration ========
        float tau = 0.f, tcur = 0.f, sc = 0.f;
        if (lwid < 2) {
            tcur = sts_s[t128];
            float tnext = (t128 < 63) ? sts_s[t128 + 1] : (tf + 1.0f);  // BOOSTER=1.0
            tau = ssig_s[t128] * (tnext - tcur) * dnorm;
            sc = tau;
#pragma unroll
            for (int off = 1; off < 32; off <<= 1) {
                float u = __shfl_up_sync(0xffffffffu, sc, off);
                if (lane >= off) sc += u;
            }
            if (lwid == 0 && lane == 31) sred_s[15] = sc;
        }
        bar_slot(slot);  // (3)
        if (lwid < 2) {
            if (lwid == 1) sc += sred_s[15];
            float excl = sc - tau;
            float wgt = __expf(-excl) * (1.f - __expf(-tau));
            float v0 = wgt * sc0_s[t128];
            float v1 = wgt * sc1_s[t128];
            float v2 = wgt * sc2_s[t128];
            float v3 = wgt;
            float v4 = wgt * tcur;
#pragma unroll
            for (int off = 16; off >= 1; off >>= 1) {
                v0 += __shfl_xor_sync(0xffffffffu, v0, off);
                v1 += __shfl_xor_sync(0xffffffffu, v1, off);
                v2 += __shfl_xor_sync(0xffffffffu, v2, off);
                v3 += __shfl_xor_sync(0xffffffffu, v3, off);
                v4 += __shfl_xor_sync(0xffffffffu, v4, off);
            }
            if (lane == 0) {
                sred_s[lwid * 5 + 0] = v0;
                sred_s[lwid * 5 + 1] = v1;
                sred_s[lwid * 5 + 2] = v2;
                sred_s[lwid * 5 + 3] = v3;
                sred_s[lwid * 5 + 4] = v4;
            }
        }
        bar_slot(slot);  // (4)
        if (t128 < 5) {
            float am = active ? 1.f : 0.f;
            out[ray * 5 + t128] = (sred_s[t128] + sred_s[5 + t128]) * am;
        }
        bar_slot(slot);  // (5) protect reused buffers
    }
}

extern "C" void kernel_launch(void* const* d_in, const int* in_sizes, int n_in,
                              void* d_out, int out_size) {
    const float* rays_o = (const float*)d_in[0];
    const float* rays_d = (const float*)d_in[1];
    const float* aabb   = (const float*)d_in[2];
    const float* W1  = (const float*)d_in[3];
    const float* b1  = (const float*)d_in[4];
    const float* W2  = (const float*)d_in[5];
    const float* b2  = (const float*)d_in[6];
    const float* Wd  = (const float*)d_in[7];
    const float* bd  = (const float*)d_in[8];
    const float* Wf  = (const float*)d_in[9];
    const float* bf  = (const float*)d_in[10];
    const float* Wc1 = (const float*)d_in[11];
    const float* bc1 = (const float*)d_in[12];
    const float* Wc2 = (const float*)d_in[13];
    const float* bc2 = (const float*)d_in[14];
    float* out = (float*)d_out;

    prep_all<<<192, 32>>>(W2, Wf, Wd, Wc1, Wc2);
    size_t smem = 26848 * sizeof(float);  // 107392 B -> 2 blocks/SM
    cudaFuncSetAttribute(radiance_kernel, cudaFuncAttributeMaxDynamicSharedMemorySize,
                         (int)smem);
    radiance_kernel<<<GRID, 256, smem>>>(rays_o, rays_d, aabb, W1, b1, W2, b2, Wd, bd,
                                         Wf, bf, Wc1, bc1, Wc2, bc2, out);
}